// round 1
// baseline (speedup 1.0000x reference)
#include <cuda_runtime.h>
#include <math.h>

// ---------------- problem constants ----------------
#define BATCH 2
#define CDIM 64
#define DI   128          // D_INNER
#define HH   128
#define WW   128
#define LL   (HH*WW)      // 16384
#define NCHC 20           // DT_RANK + 2*D_STATE
#define DTR  4
#define DST  8
#define HID  192
#define H2C  384
#define CHUNK   128
#define NCHUNK  (LL/CHUNK)   // 128

// ---------------- scratch (device globals; no allocation allowed) ----------------
__device__ float g_xf   [BATCH*CDIM*LL];
__device__ float g_xn   [BATCH*CDIM*LL];
__device__ float g_xin  [BATCH*DI*LL];
__device__ float g_z    [BATCH*DI*LL];
__device__ float g_xs   [BATCH*DI*LL];
__device__ float g_dbl0 [BATCH*NCHC*LL];
__device__ float g_dtr  [BATCH*DTR*LL];
__device__ float g_bc   [BATCH*LL*16];          // [b][p][0..7]=B, [8..15]=C
__device__ float g_delta[BATCH*DI*LL];
__device__ float g_y    [BATCH*DI*LL];
__device__ float g_t    [BATCH*DI*LL];
__device__ float g_x2   [BATCH*CDIM*LL];
__device__ float g_h2   [BATCH*H2C*LL];
__device__ float g_g    [BATCH*HID*LL];
__device__ float g_y2   [BATCH*CDIM*LL];
__device__ float g_P    [BATCH*DI*NCHUNK*DST];
__device__ float g_S    [BATCH*DI*NCHUNK*DST];
__device__ float g_hin  [BATCH*DI*NCHUNK*DST];

// twiddles for 8-point DFT
__device__ __constant__ float C8[8] = {1.f, 0.70710678118654752f, 0.f, -0.70710678118654752f,
                                      -1.f, -0.70710678118654752f, 0.f, 0.70710678118654752f};
__device__ __constant__ float S8[8] = {0.f, 0.70710678118654752f, 1.f, 0.70710678118654752f,
                                       0.f, -0.70710678118654752f, -1.f, -0.70710678118654752f};

__device__ __forceinline__ float gelu_f(float x) {
    return 0.5f * x * (1.0f + erff(x * 0.70710678118654752f));
}
__device__ __forceinline__ float softplus_f(float x) {
    return (x > 20.f) ? x : log1pf(__expf(x));
}

// ---------------- K0: flip + rmsnorm(norm1), keep flipped copy ----------------
__global__ void k_flip_rms(const float* __restrict__ x, const float* __restrict__ w,
                           const float* __restrict__ bb, float* __restrict__ xf,
                           float* __restrict__ xn) {
    int p = blockIdx.x * blockDim.x + threadIdx.x;
    int b = blockIdx.y;
    if (p >= LL) return;
    float v[CDIM];
    float ss = 0.f;
    int src = b * CDIM * LL + (LL - 1 - p);
    #pragma unroll
    for (int c = 0; c < CDIM; c++) { float t = x[src + c * LL]; v[c] = t; ss += t * t; }
    float rs = rsqrtf(ss * (1.0f / CDIM) + 1e-6f);
    int dst = b * CDIM * LL + p;
    #pragma unroll
    for (int c = 0; c < CDIM; c++) {
        xf[dst + c * LL] = v[c];
        xn[dst + c * LL] = v[c] * rs * w[c] + bb[c];
    }
}

// ---------------- K7-style: rmsnorm only ----------------
__global__ void k_rms(const float* __restrict__ x, const float* __restrict__ w,
                      const float* __restrict__ bb, float* __restrict__ xn) {
    int p = blockIdx.x * blockDim.x + threadIdx.x;
    int b = blockIdx.y;
    if (p >= LL) return;
    float v[CDIM];
    float ss = 0.f;
    int src = b * CDIM * LL + p;
    #pragma unroll
    for (int c = 0; c < CDIM; c++) { float t = x[src + c * LL]; v[c] = t; ss += t * t; }
    float rs = rsqrtf(ss * (1.0f / CDIM) + 1e-6f);
    #pragma unroll
    for (int c = 0; c < CDIM; c++) xn[src + c * LL] = v[c] * rs * w[c] + bb[c];
}

// ---------------- K1: in_proj 64->256, split into xin / z ----------------
__global__ void k_inproj(const float* __restrict__ xn, const float* __restrict__ Wg,
                         float* __restrict__ xin, float* __restrict__ z) {
    extern __shared__ float sw[];   // [256][64] row-major
    for (int i = threadIdx.x; i < 256 * 64; i += blockDim.x) sw[i] = Wg[i];
    __syncthreads();
    int t = threadIdx.x;
    int px = blockIdx.x * 128 + (t & 127);
    int og = t >> 7;   // 0 -> xin, 1 -> z
    int b = blockIdx.y;
    float xv[64];
    const float* xp = xn + b * CDIM * LL + px;
    #pragma unroll
    for (int c = 0; c < 64; c++) xv[c] = xp[c * LL];
    float* ob = (og == 0 ? xin : z) + b * DI * LL + px;
    const float4* sw4 = (const float4*)(sw + og * 128 * 64);
    #pragma unroll 4
    for (int o = 0; o < 128; o++) {
        float acc = 0.f;
        #pragma unroll
        for (int i = 0; i < 16; i++) {
            float4 w4 = sw4[o * 16 + i];
            acc += xv[4*i] * w4.x + xv[4*i+1] * w4.y + xv[4*i+2] * w4.z + xv[4*i+3] * w4.w;
        }
        ob[o * LL] = acc;
    }
}

// ---------------- K2: depthwise 3x3 + bias + gelu ----------------
__global__ void k_dwconv2_gelu(const float* __restrict__ xin, const float* __restrict__ cw,
                               const float* __restrict__ cb, float* __restrict__ xs) {
    int idx = blockIdx.x * blockDim.x + threadIdx.x;
    if (idx >= BATCH * DI * LL) return;
    int p = idx & (LL - 1);
    int d = (idx >> 14) & (DI - 1);
    int b = idx >> 21;
    int h = p >> 7, w = p & 127;
    const float* in = xin + (b * DI + d) * LL;
    const float* k = cw + d * 9;
    float acc = cb[d];
    #pragma unroll
    for (int dh = -1; dh <= 1; dh++) {
        int h2 = h + dh; if ((unsigned)h2 >= HH) continue;
        #pragma unroll
        for (int dw = -1; dw <= 1; dw++) {
            int w2 = w + dw; if ((unsigned)w2 >= WW) continue;
            acc += in[h2 * WW + w2] * k[(dh + 1) * 3 + (dw + 1)];
        }
    }
    xs[idx] = gelu_f(acc);
}

// ---------------- K3a: x_proj 128->20 ----------------
__global__ void k_xproj(const float* __restrict__ xs, const float* __restrict__ Wg,
                        float* __restrict__ out) {
    __shared__ float sw[DI * NCHC];   // transposed [d][c]
    for (int i = threadIdx.x; i < DI * NCHC; i += blockDim.x) {
        int c = i % NCHC, d = i / NCHC;
        sw[i] = Wg[c * DI + d];
    }
    __syncthreads();
    int px = blockIdx.x * blockDim.x + threadIdx.x;
    int b = blockIdx.y;
    if (px >= LL) return;
    float acc[NCHC];
    #pragma unroll
    for (int c = 0; c < NCHC; c++) acc[c] = 0.f;
    const float* xp = xs + b * DI * LL + px;
    #pragma unroll 4
    for (int d = 0; d < DI; d++) {
        float xv = xp[d * LL];
        const float4* r = (const float4*)(sw + d * NCHC);
        #pragma unroll
        for (int i = 0; i < 5; i++) {
            float4 w4 = r[i];
            acc[4*i]   += xv * w4.x; acc[4*i+1] += xv * w4.y;
            acc[4*i+2] += xv * w4.z; acc[4*i+3] += xv * w4.w;
        }
    }
    float* op = out + b * NCHC * LL + px;
    #pragma unroll
    for (int c = 0; c < NCHC; c++) op[c * LL] = acc[c];
}

// ---------------- K3b: depthwise 1d conv (k=7, pad 3) + bias; split dt rows / B,C transposed ----------------
__global__ void k_dwconv1(const float* __restrict__ in, const float* __restrict__ cw,
                          const float* __restrict__ cb, float* __restrict__ dtr,
                          float* __restrict__ bc) {
    int idx = blockIdx.x * blockDim.x + threadIdx.x;
    if (idx >= BATCH * NCHC * LL) return;
    int p = idx % LL;
    int c = (idx / LL) % NCHC;
    int b = idx / (LL * NCHC);
    const float* ip = in + (b * NCHC + c) * LL;
    const float* k = cw + c * 7;
    float acc = cb[c];
    #pragma unroll
    for (int t = -3; t <= 3; t++) {
        int pp = p + t;
        if ((unsigned)pp < LL) acc += ip[pp] * k[t + 3];
    }
    if (c < DTR) dtr[(b * DTR + c) * LL + p] = acc;
    else         bc[((long)b * LL + p) * 16 + (c - DTR)] = acc;
}

// ---------------- K4: dt projection + softplus -> delta ----------------
__global__ void k_delta(const float* __restrict__ dtr, const float* __restrict__ dtw,
                        const float* __restrict__ dtb, float* __restrict__ delta) {
    __shared__ float sw[DI * 4];
    __shared__ float sb[DI];
    for (int i = threadIdx.x; i < DI * 4; i += blockDim.x) sw[i] = dtw[i];
    for (int i = threadIdx.x; i < DI; i += blockDim.x) sb[i] = dtb[i];
    __syncthreads();
    int px = blockIdx.x * blockDim.x + threadIdx.x;
    int b = blockIdx.y;
    if (px >= LL) return;
    const float* rp = dtr + b * DTR * LL + px;
    float r0 = rp[0], r1 = rp[LL], r2 = rp[2 * LL], r3 = rp[3 * LL];
    float* op = delta + b * DI * LL + px;
    #pragma unroll 4
    for (int d = 0; d < DI; d++) {
        float4 w4 = ((const float4*)sw)[d];
        float s = r0 * w4.x + r1 * w4.y + r2 * w4.z + r3 * w4.w + sb[d];
        op[d * LL] = softplus_f(s);
    }
}

// ---------------- K5a: chunked scan pass A (local P, S) ----------------
__global__ void k_scanA(const float* __restrict__ delta, const float* __restrict__ xs,
                        const float* __restrict__ bc, const float* __restrict__ Alog,
                        float* __restrict__ P, float* __restrict__ S) {
    int tid = blockIdx.x * blockDim.x + threadIdx.x;   // B*DI*NCHUNK*8
    int n = tid & 7;
    int r = tid >> 3;
    int chunk = r & (NCHUNK - 1);
    int bd = r >> 7;
    int d = bd & (DI - 1);
    float An = -__expf(Alog[d * DST + n]);
    int b = bd >> 7;
    const float* dp = delta + bd * LL + chunk * CHUNK;
    const float* xp = xs + bd * LL + chunk * CHUNK;
    const float* bp = bc + ((long)b * LL + chunk * CHUNK) * 16 + n;
    float Pv = 1.f, Sv = 0.f;
    #pragma unroll 4
    for (int t = 0; t < CHUNK; t++) {
        float dl = dp[t], xv = xp[t];
        float a = __expf(dl * An);
        float bx = dl * xv * bp[t * 16];
        Pv *= a;
        Sv = a * Sv + bx;
    }
    int o = (bd * NCHUNK + chunk) * 8 + n;
    P[o] = Pv; S[o] = Sv;
}

// ---------------- K5b: scan across chunks ----------------
__global__ void k_scanB(const float* __restrict__ P, const float* __restrict__ S,
                        float* __restrict__ hin) {
    int tid = blockIdx.x * blockDim.x + threadIdx.x;  // B*DI*8 = 2048
    int n = tid & 7;
    int bd = tid >> 3;
    float h = 0.f;
    int base = bd * NCHUNK * 8 + n;
    for (int c = 0; c < NCHUNK; c++) {
        int o = base + c * 8;
        hin[o] = h;
        h = P[o] * h + S[o];
    }
}

// ---------------- K5c: pass C — recompute with true h_in, emit y ----------------
__global__ void k_scanC(const float* __restrict__ delta, const float* __restrict__ xs,
                        const float* __restrict__ bc, const float* __restrict__ Alog,
                        const float* __restrict__ Ds, const float* __restrict__ hin,
                        float* __restrict__ y) {
    int tid = blockIdx.x * blockDim.x + threadIdx.x;
    int n = tid & 7;
    int r = tid >> 3;
    int chunk = r & (NCHUNK - 1);
    int bd = r >> 7;
    int d = bd & (DI - 1);
    int b = bd >> 7;
    float An = -__expf(Alog[d * DST + n]);
    float Dd = Ds[d];
    const float* dp = delta + bd * LL + chunk * CHUNK;
    const float* xp = xs + bd * LL + chunk * CHUNK;
    const float* bp = bc + ((long)b * LL + chunk * CHUNK) * 16 + n;
    const float* cp = bp + 8;
    float h = hin[(bd * NCHUNK + chunk) * 8 + n];
    float* yp = y + bd * LL + chunk * CHUNK;
    #pragma unroll 2
    for (int t = 0; t < CHUNK; t++) {
        float dl = dp[t], xv = xp[t];
        float a = __expf(dl * An);
        float bx = dl * xv * bp[t * 16];
        h = a * h + bx;
        float yv = h * cp[t * 16];
        yv += __shfl_xor_sync(0xffffffffu, yv, 1);
        yv += __shfl_xor_sync(0xffffffffu, yv, 2);
        yv += __shfl_xor_sync(0xffffffffu, yv, 4);
        if (n == 0) yp[t] = yv + Dd * xv;
    }
}

// ---------------- K6a: LayerNorm(d=128) * gelu(z) ----------------
__global__ void k_lngelu(const float* __restrict__ y, const float* __restrict__ z,
                         const float* __restrict__ w, const float* __restrict__ bb,
                         float* __restrict__ tout) {
    __shared__ float sww[DI], sbb[DI];
    for (int i = threadIdx.x; i < DI; i += blockDim.x) { sww[i] = w[i]; sbb[i] = bb[i]; }
    __syncthreads();
    int px = blockIdx.x * blockDim.x + threadIdx.x;
    int b = blockIdx.y;
    if (px >= LL) return;
    const float* yp = y + b * DI * LL + px;
    float s = 0.f, s2 = 0.f;
    #pragma unroll 4
    for (int d = 0; d < DI; d++) { float v = yp[d * LL]; s += v; s2 += v * v; }
    float mu = s * (1.f / DI);
    float var = fmaxf(s2 * (1.f / DI) - mu * mu, 0.f);
    float rs = rsqrtf(var + 1e-5f);
    const float* zp = z + b * DI * LL + px;
    float* op = tout + b * DI * LL + px;
    #pragma unroll 4
    for (int d = 0; d < DI; d++) {
        float v = (yp[d * LL] - mu) * rs * sww[d] + sbb[d];
        op[d * LL] = v * gelu_f(zp[d * LL]);
    }
}

// ---------------- K6b: out_proj 128->64 + residual ----------------
__global__ void k_outproj(const float* __restrict__ tin, const float* __restrict__ Wg,
                          const float* __restrict__ xf, float* __restrict__ x2) {
    __shared__ float sw[DI * CDIM];   // transposed [d][o]
    for (int i = threadIdx.x; i < DI * CDIM; i += blockDim.x) {
        int o = i & 63, d = i >> 6;
        sw[i] = Wg[o * DI + d];
    }
    __syncthreads();
    int px = blockIdx.x * blockDim.x + threadIdx.x;
    int b = blockIdx.y;
    if (px >= LL) return;
    float acc[CDIM];
    #pragma unroll
    for (int o = 0; o < CDIM; o++) acc[o] = 0.f;
    const float* tp = tin + b * DI * LL + px;
    #pragma unroll 2
    for (int d = 0; d < DI; d++) {
        float tv = tp[d * LL];
        const float4* r = (const float4*)(sw + d * CDIM);
        #pragma unroll
        for (int i = 0; i < 16; i++) {
            float4 w4 = r[i];
            acc[4*i]   += tv * w4.x; acc[4*i+1] += tv * w4.y;
            acc[4*i+2] += tv * w4.z; acc[4*i+3] += tv * w4.w;
        }
    }
    const float* xp = xf + b * CDIM * LL + px;
    float* op = x2 + b * CDIM * LL + px;
    #pragma unroll
    for (int o = 0; o < CDIM; o++) op[o * LL] = acc[o] + xp[o * LL];
}

// ---------------- K8: pin 64->384 ----------------
__global__ void k_pin(const float* __restrict__ xn, const float* __restrict__ Wg,
                      float* __restrict__ h2) {
    extern __shared__ float sw[];   // [384][64]
    for (int i = threadIdx.x; i < H2C * 64; i += blockDim.x) sw[i] = Wg[i];
    __syncthreads();
    int t = threadIdx.x;
    int px = blockIdx.x * 128 + (t & 127);
    int og = t >> 7;
    int b = blockIdx.y;
    float xv[64];
    const float* xp = xn + b * CDIM * LL + px;
    #pragma unroll
    for (int c = 0; c < 64; c++) xv[c] = xp[c * LL];
    float* ob = h2 + ((long)b * H2C + og * HID) * LL + px;
    const float4* sw4 = (const float4*)(sw + og * HID * 64);
    #pragma unroll 4
    for (int o = 0; o < HID; o++) {
        float acc = 0.f;
        #pragma unroll
        for (int i = 0; i < 16; i++) {
            float4 w4 = sw4[o * 16 + i];
            acc += xv[4*i] * w4.x + xv[4*i+1] * w4.y + xv[4*i+2] * w4.z + xv[4*i+3] * w4.w;
        }
        ob[o * LL] = acc;
    }
}

// ---------------- K9: depthwise 3x3 on h2 (no bias) + GLU gate ----------------
__global__ void k_dwconv_glu(const float* __restrict__ h2, const float* __restrict__ dw,
                             float* __restrict__ g) {
    int idx = blockIdx.x * blockDim.x + threadIdx.x;
    if (idx >= BATCH * HID * LL) return;
    int p = idx & (LL - 1);
    int o = (idx >> 14) % HID;
    int b = idx / (HID * LL);
    int h = p >> 7, w = p & 127;
    const float* inA = h2 + ((long)b * H2C + o) * LL;
    const float* inB = h2 + ((long)b * H2C + HID + o) * LL;
    const float* kA = dw + o * 9;
    const float* kB = dw + (HID + o) * 9;
    float a = 0.f, c2 = 0.f;
    #pragma unroll
    for (int dh = -1; dh <= 1; dh++) {
        int h2i = h + dh; if ((unsigned)h2i >= HH) continue;
        #pragma unroll
        for (int dwi = -1; dwi <= 1; dwi++) {
            int w2 = w + dwi; if ((unsigned)w2 >= WW) continue;
            float va = inA[h2i * WW + w2];
            float vb = inB[h2i * WW + w2];
            int ki = (dh + 1) * 3 + (dwi + 1);
            a  += va * kA[ki];
            c2 += vb * kB[ki];
        }
    }
    g[((long)b * HID + o) * LL + p] = gelu_f(a) * c2;
}

// ---------------- K10: pout 192->64 ----------------
__global__ void k_pout(const float* __restrict__ gg, const float* __restrict__ Wg,
                       float* __restrict__ y2) {
    extern __shared__ float sw[];   // transposed [d][o], 192*64
    for (int i = threadIdx.x; i < HID * CDIM; i += blockDim.x) {
        int o = i & 63, d = i >> 6;
        sw[i] = Wg[o * HID + d];
    }
    __syncthreads();
    int px = blockIdx.x * blockDim.x + threadIdx.x;
    int b = blockIdx.y;
    if (px >= LL) return;
    float acc[CDIM];
    #pragma unroll
    for (int o = 0; o < CDIM; o++) acc[o] = 0.f;
    const float* gp = gg + (long)b * HID * LL + px;
    #pragma unroll 2
    for (int d = 0; d < HID; d++) {
        float gv = gp[d * LL];
        const float4* r = (const float4*)(sw + d * CDIM);
        #pragma unroll
        for (int i = 0; i < 16; i++) {
            float4 w4 = r[i];
            acc[4*i]   += gv * w4.x; acc[4*i+1] += gv * w4.y;
            acc[4*i+2] += gv * w4.z; acc[4*i+3] += gv * w4.w;
        }
    }
    float* op = y2 + b * CDIM * LL + px;
    #pragma unroll
    for (int o = 0; o < CDIM; o++) op[o * LL] = acc[o];
}

// ---------------- K11: per-patch 8x8 rfft2 * s -> irfft2, + residual ----------------
__global__ void __launch_bounds__(64) k_fft(const float* __restrict__ y2,
                                            const float* __restrict__ x2,
                                            const float* __restrict__ fp,
                                            float* __restrict__ out) {
    int tid = blockIdx.x * blockDim.x + threadIdx.x;  // B*C*16*16 = 32768
    int pw = tid & 15;
    int ph = (tid >> 4) & 15;
    int c = (tid >> 8) & 63;
    int b = tid >> 14;
    const float* base = y2 + ((long)b * CDIM + c) * LL + (ph * 8) * WW + pw * 8;
    float pr[8][8];
    #pragma unroll
    for (int i = 0; i < 8; i++)
        #pragma unroll
        for (int j = 0; j < 8; j++) pr[i][j] = base[i * WW + j];

    // fft over rows-axis (h), real input
    float Gr[8][8], Gi[8][8];
    #pragma unroll
    for (int j = 0; j < 8; j++) {
        #pragma unroll
        for (int h = 0; h < 8; h++) {
            float sr = 0.f, si = 0.f;
            #pragma unroll
            for (int i = 0; i < 8; i++) {
                int k = (h * i) & 7;
                sr += pr[i][j] * C8[k];
                si -= pr[i][j] * S8[k];
            }
            Gr[h][j] = sr; Gi[h][j] = si;
        }
    }
    // rfft over cols-axis (w<=4), then scale by s (real)
    float Xr[8][5], Xi[8][5];
    const float* sp = fp + c * 40;
    #pragma unroll
    for (int h = 0; h < 8; h++) {
        #pragma unroll
        for (int w = 0; w < 5; w++) {
            float sr = 0.f, si = 0.f;
            #pragma unroll
            for (int j = 0; j < 8; j++) {
                int k = (w * j) & 7;
                float cr = C8[k], ci = -S8[k];
                sr += Gr[h][j] * cr - Gi[h][j] * ci;
                si += Gr[h][j] * ci + Gi[h][j] * cr;
            }
            float sc = sp[h * 5 + w];
            Xr[h][w] = sr * sc; Xi[h][w] = si * sc;
        }
    }
    // ifft over h (no 1/8; folded at end)
    float Kr[8][5], Ki[8][5];
    #pragma unroll
    for (int w = 0; w < 5; w++) {
        #pragma unroll
        for (int h = 0; h < 8; h++) {
            float sr = 0.f, si = 0.f;
            #pragma unroll
            for (int m = 0; m < 8; m++) {
                int k = (h * m) & 7;
                float cr = C8[k], ci = S8[k];
                sr += Xr[m][w] * cr - Xi[m][w] * ci;
                si += Xr[m][w] * ci + Xi[m][w] * cr;
            }
            Kr[h][w] = sr; Ki[h][w] = si;
        }
    }
    // irfft over w (Hermitian; Re-only of DC/Nyquist) + residual; total scale 1/64
    const float* xp = x2 + ((long)b * CDIM + c) * LL + (ph * 8) * WW + pw * 8;
    float* op = out + ((long)b * CDIM + c) * LL + (ph * 8) * WW + pw * 8;
    #pragma unroll
    for (int i = 0; i < 8; i++) {
        #pragma unroll
        for (int j = 0; j < 8; j++) {
            float v = Kr[i][0] + ((j & 1) ? -Kr[i][4] : Kr[i][4]);
            #pragma unroll
            for (int w = 1; w < 4; w++) {
                int k = (w * j) & 7;
                v += 2.f * (Kr[i][w] * C8[k] - Ki[i][w] * S8[k]);
            }
            op[i * WW + j] = xp[i * WW + j] + v * (1.f / 64.f);
        }
    }
}

// ---------------- host launch ----------------
extern "C" void kernel_launch(void* const* d_in, const int* in_sizes, int n_in,
                              void* d_out, int out_size) {
    const float* x        = (const float*)d_in[0];
    const float* n1w      = (const float*)d_in[1];
    const float* n1b      = (const float*)d_in[2];
    const float* inprojw  = (const float*)d_in[3];
    const float* conv2dw  = (const float*)d_in[4];
    const float* conv2db  = (const float*)d_in[5];
    const float* xprojw   = (const float*)d_in[6];
    const float* xconvw   = (const float*)d_in[7];
    const float* xconvb   = (const float*)d_in[8];
    const float* dtpw     = (const float*)d_in[9];
    const float* dtpb     = (const float*)d_in[10];
    const float* Alogs    = (const float*)d_in[11];
    const float* Ds       = (const float*)d_in[12];
    const float* onw      = (const float*)d_in[13];
    const float* onb      = (const float*)d_in[14];
    const float* outprojw = (const float*)d_in[15];
    const float* n2w      = (const float*)d_in[16];
    const float* n2b      = (const float*)d_in[17];
    const float* pinw     = (const float*)d_in[18];
    const float* dww      = (const float*)d_in[19];
    const float* fftp     = (const float*)d_in[20];
    const float* poutw    = (const float*)d_in[21];
    float* out = (float*)d_out;

    // resolve scratch symbols
    float *xf, *xn, *xin, *z, *xs, *dbl0, *dtr, *bc, *delta, *y, *t, *x2, *h2, *g, *y2, *P, *S, *hin;
    cudaGetSymbolAddress((void**)&xf, g_xf);
    cudaGetSymbolAddress((void**)&xn, g_xn);
    cudaGetSymbolAddress((void**)&xin, g_xin);
    cudaGetSymbolAddress((void**)&z, g_z);
    cudaGetSymbolAddress((void**)&xs, g_xs);
    cudaGetSymbolAddress((void**)&dbl0, g_dbl0);
    cudaGetSymbolAddress((void**)&dtr, g_dtr);
    cudaGetSymbolAddress((void**)&bc, g_bc);
    cudaGetSymbolAddress((void**)&delta, g_delta);
    cudaGetSymbolAddress((void**)&y, g_y);
    cudaGetSymbolAddress((void**)&t, g_t);
    cudaGetSymbolAddress((void**)&x2, g_x2);
    cudaGetSymbolAddress((void**)&h2, g_h2);
    cudaGetSymbolAddress((void**)&g, g_g);
    cudaGetSymbolAddress((void**)&y2, g_y2);
    cudaGetSymbolAddress((void**)&P, g_P);
    cudaGetSymbolAddress((void**)&S, g_S);
    cudaGetSymbolAddress((void**)&hin, g_hin);

    cudaFuncSetAttribute(k_inproj, cudaFuncAttributeMaxDynamicSharedMemorySize, 256 * 64 * 4);
    cudaFuncSetAttribute(k_pin,   cudaFuncAttributeMaxDynamicSharedMemorySize, 384 * 64 * 4);
    cudaFuncSetAttribute(k_pout,  cudaFuncAttributeMaxDynamicSharedMemorySize, 192 * 64 * 4);

    dim3 px128(LL / 128, BATCH);

    k_flip_rms<<<px128, 128>>>(x, n1w, n1b, xf, xn);
    k_inproj<<<dim3(LL / 128, BATCH), 256, 256 * 64 * 4>>>(xn, inprojw, xin, z);
    k_dwconv2_gelu<<<(BATCH * DI * LL) / 256, 256>>>(xin, conv2dw, conv2db, xs);
    k_xproj<<<px128, 128>>>(xs, xprojw, dbl0);
    k_dwconv1<<<(BATCH * NCHC * LL) / 256, 256>>>(dbl0, xconvw, xconvb, dtr, bc);
    k_delta<<<px128, 128>>>(dtr, dtpw, dtpb, delta);
    k_scanA<<<(BATCH * DI * NCHUNK * DST) / 256, 256>>>(delta, xs, bc, Alogs, P, S);
    k_scanB<<<(BATCH * DI * DST) / 256, 256>>>(P, S, hin);
    k_scanC<<<(BATCH * DI * NCHUNK * DST) / 256, 256>>>(delta, xs, bc, Alogs, Ds, hin, y);
    k_lngelu<<<px128, 128>>>(y, z, onw, onb, t);
    k_outproj<<<px128, 128>>>(t, outprojw, xf, x2);
    k_rms<<<px128, 128>>>(x2, n2w, n2b, xn);
    k_pin<<<dim3(LL / 128, BATCH), 256, 384 * 64 * 4>>>(xn, pinw, h2);
    k_dwconv_glu<<<(BATCH * HID * LL) / 256, 256>>>(h2, dww, g);
    k_pout<<<px128, 128, 192 * 64 * 4>>>(g, poutw, y2);
    k_fft<<<(BATCH * CDIM * 16 * 16) / 64, 64>>>(y2, x2, fftp, out);

    (void)in_sizes; (void)n_in; (void)out_size;
}

// round 3
// speedup vs baseline: 1.2817x; 1.2817x over previous
#include <cuda_runtime.h>
#include <math.h>

// ---------------- problem constants ----------------
#define BATCH 2
#define CDIM 64
#define DI   128          // D_INNER
#define HH   128
#define WW   128
#define LL   (HH*WW)      // 16384
#define NCHC 20           // DT_RANK + 2*D_STATE
#define DTR  4
#define DST  8
#define HID  192
#define H2C  384
#define CHUNK   128
#define NCHUNK  (LL/CHUNK)   // 128

// ---------------- scratch (device globals; no allocation allowed) ----------------
__device__ float g_xf   [BATCH*CDIM*LL];
__device__ float g_xn   [BATCH*CDIM*LL];
__device__ float g_xin  [BATCH*DI*LL];
__device__ float g_z    [BATCH*DI*LL];
__device__ float g_xs   [BATCH*DI*LL];
__device__ float g_dbl0 [BATCH*NCHC*LL];
__device__ float g_dtr  [BATCH*DTR*LL];
__device__ float g_bc   [BATCH*LL*16];          // [b][p][0..7]=B, [8..15]=C
__device__ float g_delta[BATCH*DI*LL];
__device__ float g_y    [BATCH*DI*LL];
__device__ float g_t    [BATCH*DI*LL];
__device__ float g_x2   [BATCH*CDIM*LL];
__device__ float g_h2   [BATCH*H2C*LL];
__device__ float g_g    [BATCH*HID*LL];
__device__ float g_y2   [BATCH*CDIM*LL];
__device__ float g_P    [BATCH*DI*NCHUNK*DST];
__device__ float g_S    [BATCH*DI*NCHUNK*DST];
__device__ float g_hin  [BATCH*DI*NCHUNK*DST];

// twiddles for 8-point DFT
__device__ __constant__ float C8[8] = {1.f, 0.70710678118654752f, 0.f, -0.70710678118654752f,
                                      -1.f, -0.70710678118654752f, 0.f, 0.70710678118654752f};
__device__ __constant__ float S8[8] = {0.f, 0.70710678118654752f, 1.f, 0.70710678118654752f,
                                       0.f, -0.70710678118654752f, -1.f, -0.70710678118654752f};

__device__ __forceinline__ float gelu_f(float x) {
    return 0.5f * x * (1.0f + erff(x * 0.70710678118654752f));
}
__device__ __forceinline__ float softplus_f(float x) {
    return (x > 20.f) ? x : log1pf(__expf(x));
}

// =====================================================================
// Tiled GEMM core: block computes outputs [o0..o0+63] x pixels [p0..p0+127].
// 256 threads; thread (tx,ty) = 4 px (tx) x 8 outs (ty). K in chunks of 64.
// Xb: input base (batch offset + p0 applied), channel-major stride LL.
// Wo: weight rows, row-major [out][K], already offset by o0*K.
// =====================================================================
template<int K>
__device__ __forceinline__ void gemm_tile_core(const float* __restrict__ Xb,
                                               const float* __restrict__ Wo,
                                               float* s_x, float* s_w,
                                               float4 (&acc)[8]) {
    const int t  = threadIdx.x;
    const int tx = t & 31;
    const int ty = t >> 5;
    #pragma unroll
    for (int j = 0; j < 8; j++) acc[j] = make_float4(0.f, 0.f, 0.f, 0.f);

    for (int kc = 0; kc < K; kc += 64) {
        __syncthreads();
        // load x tile [64 ch][128 px] : coalesced float4
        {
            const int col4 = t & 31;
            const int c0   = t >> 5;
            #pragma unroll
            for (int r = 0; r < 8; r++) {
                int c = c0 + r * 8;
                *(float4*)(s_x + c * 128 + col4 * 4) =
                    *(const float4*)(Xb + (kc + c) * LL + col4 * 4);
            }
        }
        // load w tile transposed: s_w[k][o], k in [0,64), o in [0,64)
        {
            const int o   = t >> 2;
            const int k4b = t & 3;
            #pragma unroll
            for (int r = 0; r < 4; r++) {
                int k4 = k4b + r * 4;
                float4 v = *(const float4*)(Wo + o * K + kc + k4 * 4);
                s_w[(k4 * 4 + 0) * 64 + o] = v.x;
                s_w[(k4 * 4 + 1) * 64 + o] = v.y;
                s_w[(k4 * 4 + 2) * 64 + o] = v.z;
                s_w[(k4 * 4 + 3) * 64 + o] = v.w;
            }
        }
        __syncthreads();
        #pragma unroll 16
        for (int c = 0; c < 64; c++) {
            float4 xv = *(const float4*)(s_x + c * 128 + tx * 4);
            float4 wa = *(const float4*)(s_w + c * 64 + ty * 8);
            float4 wb = *(const float4*)(s_w + c * 64 + ty * 8 + 4);
            acc[0].x += wa.x * xv.x; acc[0].y += wa.x * xv.y; acc[0].z += wa.x * xv.z; acc[0].w += wa.x * xv.w;
            acc[1].x += wa.y * xv.x; acc[1].y += wa.y * xv.y; acc[1].z += wa.y * xv.z; acc[1].w += wa.y * xv.w;
            acc[2].x += wa.z * xv.x; acc[2].y += wa.z * xv.y; acc[2].z += wa.z * xv.z; acc[2].w += wa.z * xv.w;
            acc[3].x += wa.w * xv.x; acc[3].y += wa.w * xv.y; acc[3].z += wa.w * xv.z; acc[3].w += wa.w * xv.w;
            acc[4].x += wb.x * xv.x; acc[4].y += wb.x * xv.y; acc[4].z += wb.x * xv.z; acc[4].w += wb.x * xv.w;
            acc[5].x += wb.y * xv.x; acc[5].y += wb.y * xv.y; acc[5].z += wb.y * xv.z; acc[5].w += wb.y * xv.w;
            acc[6].x += wb.z * xv.x; acc[6].y += wb.z * xv.y; acc[6].z += wb.z * xv.z; acc[6].w += wb.z * xv.w;
            acc[7].x += wb.w * xv.x; acc[7].y += wb.w * xv.y; acc[7].z += wb.w * xv.z; acc[7].w += wb.w * xv.w;
        }
    }
}

// ---------------- K1: in_proj 64->256, split into xin / z ----------------
__global__ void __launch_bounds__(256) k_inproj(const float* __restrict__ xn,
                                                const float* __restrict__ W,
                                                float* __restrict__ xin,
                                                float* __restrict__ z) {
    __shared__ float s_x[64 * 128];
    __shared__ float s_w[64 * 64];
    const int b = blockIdx.z, oz = blockIdx.y, p0 = blockIdx.x * 128;
    float4 acc[8];
    gemm_tile_core<64>(xn + b * CDIM * LL + p0, W + oz * 64 * 64, s_x, s_w, acc);
    const int tx = threadIdx.x & 31, ty = threadIdx.x >> 5;
    const int og = oz * 64 + ty * 8;
    float* dst = (og < DI) ? (xin + (long)b * DI * LL + og * LL)
                           : (z + (long)b * DI * LL + (og - DI) * LL);
    #pragma unroll
    for (int j = 0; j < 8; j++)
        *(float4*)(dst + j * LL + p0 + tx * 4) = acc[j];
}

// ---------------- K8: pin 64->384 ----------------
__global__ void __launch_bounds__(256) k_pin(const float* __restrict__ xn,
                                             const float* __restrict__ W,
                                             float* __restrict__ h2) {
    __shared__ float s_x[64 * 128];
    __shared__ float s_w[64 * 64];
    const int b = blockIdx.z, oz = blockIdx.y, p0 = blockIdx.x * 128;
    float4 acc[8];
    gemm_tile_core<64>(xn + b * CDIM * LL + p0, W + oz * 64 * 64, s_x, s_w, acc);
    const int tx = threadIdx.x & 31, ty = threadIdx.x >> 5;
    const int og = oz * 64 + ty * 8;
    float* dst = h2 + (long)b * H2C * LL + (long)og * LL;
    #pragma unroll
    for (int j = 0; j < 8; j++)
        *(float4*)(dst + j * LL + p0 + tx * 4) = acc[j];
}

// ---------------- K6b: out_proj 128->64 + residual ----------------
__global__ void __launch_bounds__(256) k_outproj(const float* __restrict__ tin,
                                                 const float* __restrict__ W,
                                                 const float* __restrict__ xf,
                                                 float* __restrict__ x2) {
    __shared__ float s_x[64 * 128];
    __shared__ float s_w[64 * 64];
    const int b = blockIdx.z, p0 = blockIdx.x * 128;
    float4 acc[8];
    gemm_tile_core<128>(tin + (long)b * DI * LL + p0, W, s_x, s_w, acc);
    const int tx = threadIdx.x & 31, ty = threadIdx.x >> 5;
    const float* xp = xf + (long)b * CDIM * LL + (ty * 8) * LL + p0 + tx * 4;
    float* dst = x2 + (long)b * CDIM * LL + (ty * 8) * LL + p0 + tx * 4;
    #pragma unroll
    for (int j = 0; j < 8; j++) {
        float4 r = *(const float4*)(xp + j * LL);
        acc[j].x += r.x; acc[j].y += r.y; acc[j].z += r.z; acc[j].w += r.w;
        *(float4*)(dst + j * LL) = acc[j];
    }
}

// ---------------- K10: pout 192->64 ----------------
__global__ void __launch_bounds__(256) k_pout(const float* __restrict__ gg,
                                              const float* __restrict__ W,
                                              float* __restrict__ y2) {
    __shared__ float s_x[64 * 128];
    __shared__ float s_w[64 * 64];
    const int b = blockIdx.z, p0 = blockIdx.x * 128;
    float4 acc[8];
    gemm_tile_core<192>(gg + (long)b * HID * LL + p0, W, s_x, s_w, acc);
    const int tx = threadIdx.x & 31, ty = threadIdx.x >> 5;
    float* dst = y2 + (long)b * CDIM * LL + (ty * 8) * LL + p0 + tx * 4;
    #pragma unroll
    for (int j = 0; j < 8; j++)
        *(float4*)(dst + j * LL) = acc[j];
}

// ---------------- K3a: x_proj 128->20 (20 outs x 256 px tile) ----------------
__global__ void __launch_bounds__(128) k_xproj(const float* __restrict__ xs,
                                               const float* __restrict__ Wg,
                                               float* __restrict__ out) {
    __shared__ float s_x[32 * 256];   // 32KB
    __shared__ float s_w[DI * NCHC];  // transposed [d][c], 10KB
    const int t = threadIdx.x;        // 128 threads, 2 px each
    const int b = blockIdx.y, p0 = blockIdx.x * 256;
    for (int i = t; i < DI * NCHC; i += 128) {
        int c = i % NCHC, d = i / NCHC;
        s_w[i] = Wg[c * DI + d];
    }
    float2 acc[NCHC];
    #pragma unroll
    for (int c = 0; c < NCHC; c++) acc[c] = make_float2(0.f, 0.f);
    const float* Xb = xs + (long)b * DI * LL + p0;
    for (int kc = 0; kc < DI; kc += 32) {
        __syncthreads();
        const int col4 = t & 63;
        const int c0   = t >> 6;
        #pragma unroll
        for (int r = 0; r < 16; r++) {
            int c = c0 + r * 2;
            *(float4*)(s_x + c * 256 + col4 * 4) =
                *(const float4*)(Xb + (kc + c) * LL + col4 * 4);
        }
        __syncthreads();
        #pragma unroll 8
        for (int c = 0; c < 32; c++) {
            float2 xv = *(const float2*)(s_x + c * 256 + t * 2);
            const float* wr = s_w + (kc + c) * NCHC;
            #pragma unroll
            for (int i = 0; i < 5; i++) {
                float4 w4 = *(const float4*)(wr + i * 4);
                acc[4*i+0].x += w4.x * xv.x; acc[4*i+0].y += w4.x * xv.y;
                acc[4*i+1].x += w4.y * xv.x; acc[4*i+1].y += w4.y * xv.y;
                acc[4*i+2].x += w4.z * xv.x; acc[4*i+2].y += w4.z * xv.y;
                acc[4*i+3].x += w4.w * xv.x; acc[4*i+3].y += w4.w * xv.y;
            }
        }
    }
    float* op = out + (long)b * NCHC * LL + p0 + t * 2;
    #pragma unroll
    for (int c = 0; c < NCHC; c++)
        *(float2*)(op + c * LL) = acc[c];
}

// ---------------- K0: flip + rmsnorm(norm1), keep flipped copy ----------------
__global__ void k_flip_rms(const float* __restrict__ x, const float* __restrict__ w,
                           const float* __restrict__ bb, float* __restrict__ xf,
                           float* __restrict__ xn) {
    int p = blockIdx.x * blockDim.x + threadIdx.x;
    int b = blockIdx.y;
    if (p >= LL) return;
    float v[CDIM];
    float ss = 0.f;
    int src = b * CDIM * LL + (LL - 1 - p);
    #pragma unroll
    for (int c = 0; c < CDIM; c++) { float t = x[src + c * LL]; v[c] = t; ss += t * t; }
    float rs = rsqrtf(ss * (1.0f / CDIM) + 1e-6f);
    int dst = b * CDIM * LL + p;
    #pragma unroll
    for (int c = 0; c < CDIM; c++) {
        xf[dst + c * LL] = v[c];
        xn[dst + c * LL] = v[c] * rs * w[c] + bb[c];
    }
}

// ---------------- rmsnorm only ----------------
__global__ void k_rms(const float* __restrict__ x, const float* __restrict__ w,
                      const float* __restrict__ bb, float* __restrict__ xn) {
    int p = blockIdx.x * blockDim.x + threadIdx.x;
    int b = blockIdx.y;
    if (p >= LL) return;
    float v[CDIM];
    float ss = 0.f;
    int src = b * CDIM * LL + p;
    #pragma unroll
    for (int c = 0; c < CDIM; c++) { float t = x[src + c * LL]; v[c] = t; ss += t * t; }
    float rs = rsqrtf(ss * (1.0f / CDIM) + 1e-6f);
    #pragma unroll
    for (int c = 0; c < CDIM; c++) xn[src + c * LL] = v[c] * rs * w[c] + bb[c];
}

// ---------------- K2: depthwise 3x3 + bias + gelu ----------------
__global__ void k_dwconv2_gelu(const float* __restrict__ xin, const float* __restrict__ cw,
                               const float* __restrict__ cb, float* __restrict__ xs) {
    int idx = blockIdx.x * blockDim.x + threadIdx.x;
    if (idx >= BATCH * DI * LL) return;
    int p = idx & (LL - 1);
    int d = (idx >> 14) & (DI - 1);
    int b = idx >> 21;
    int h = p >> 7, w = p & 127;
    const float* in = xin + (b * DI + d) * LL;
    const float* k = cw + d * 9;
    float acc = cb[d];
    #pragma unroll
    for (int dh = -1; dh <= 1; dh++) {
        int h2 = h + dh; if ((unsigned)h2 >= HH) continue;
        #pragma unroll
        for (int dw = -1; dw <= 1; dw++) {
            int w2 = w + dw; if ((unsigned)w2 >= WW) continue;
            acc += in[h2 * WW + w2] * k[(dh + 1) * 3 + (dw + 1)];
        }
    }
    xs[idx] = gelu_f(acc);
}

// ---------------- K3b: depthwise 1d conv (k=7, pad 3) + bias ----------------
__global__ void k_dwconv1(const float* __restrict__ in, const float* __restrict__ cw,
                          const float* __restrict__ cb, float* __restrict__ dtr,
                          float* __restrict__ bc) {
    int idx = blockIdx.x * blockDim.x + threadIdx.x;
    if (idx >= BATCH * NCHC * LL) return;
    int p = idx % LL;
    int c = (idx / LL) % NCHC;
    int b = idx / (LL * NCHC);
    const float* ip = in + (b * NCHC + c) * LL;
    const float* k = cw + c * 7;
    float acc = cb[c];
    #pragma unroll
    for (int t = -3; t <= 3; t++) {
        int pp = p + t;
        if ((unsigned)pp < LL) acc += ip[pp] * k[t + 3];
    }
    if (c < DTR) dtr[(b * DTR + c) * LL + p] = acc;
    else         bc[((long)b * LL + p) * 16 + (c - DTR)] = acc;
}

// ---------------- K4: dt projection + softplus -> delta ----------------
__global__ void k_delta(const float* __restrict__ dtr, const float* __restrict__ dtw,
                        const float* __restrict__ dtb, float* __restrict__ delta) {
    __shared__ float sw[DI * 4];
    __shared__ float sb[DI];
    for (int i = threadIdx.x; i < DI * 4; i += blockDim.x) sw[i] = dtw[i];
    for (int i = threadIdx.x; i < DI; i += blockDim.x) sb[i] = dtb[i];
    __syncthreads();
    int px = blockIdx.x * blockDim.x + threadIdx.x;
    int b = blockIdx.y;
    if (px >= LL) return;
    const float* rp = dtr + b * DTR * LL + px;
    float r0 = rp[0], r1 = rp[LL], r2 = rp[2 * LL], r3 = rp[3 * LL];
    float* op = delta + b * DI * LL + px;
    #pragma unroll 4
    for (int d = 0; d < DI; d++) {
        float4 w4 = ((const float4*)sw)[d];
        float s = r0 * w4.x + r1 * w4.y + r2 * w4.z + r3 * w4.w + sb[d];
        op[d * LL] = softplus_f(s);
    }
}

// ---------------- K5a: chunked scan pass A (local P, S) ----------------
__global__ void k_scanA(const float* __restrict__ delta, const float* __restrict__ xs,
                        const float* __restrict__ bc, const float* __restrict__ Alog,
                        float* __restrict__ P, float* __restrict__ S) {
    int tid = blockIdx.x * blockDim.x + threadIdx.x;
    int n = tid & 7;
    int r = tid >> 3;
    int chunk = r & (NCHUNK - 1);
    int bd = r >> 7;
    int d = bd & (DI - 1);
    float An = -__expf(Alog[d * DST + n]);
    int b = bd >> 7;
    const float* dp = delta + bd * LL + chunk * CHUNK;
    const float* xp = xs + bd * LL + chunk * CHUNK;
    const float* bp = bc + ((long)b * LL + chunk * CHUNK) * 16 + n;
    float Pv = 1.f, Sv = 0.f;
    #pragma unroll 4
    for (int t = 0; t < CHUNK; t++) {
        float dl = dp[t], xv = xp[t];
        float a = __expf(dl * An);
        float bx = dl * xv * bp[t * 16];
        Pv *= a;
        Sv = a * Sv + bx;
    }
    int o = (bd * NCHUNK + chunk) * 8 + n;
    P[o] = Pv; S[o] = Sv;
}

// ---------------- K5b: scan across chunks ----------------
__global__ void k_scanB(const float* __restrict__ P, const float* __restrict__ S,
                        float* __restrict__ hin) {
    int tid = blockIdx.x * blockDim.x + threadIdx.x;
    int n = tid & 7;
    int bd = tid >> 3;
    float h = 0.f;
    int base = bd * NCHUNK * 8 + n;
    for (int c = 0; c < NCHUNK; c++) {
        int o = base + c * 8;
        hin[o] = h;
        h = P[o] * h + S[o];
    }
}

// ---------------- K5c: pass C — recompute with true h_in, emit y ----------------
__global__ void k_scanC(const float* __restrict__ delta, const float* __restrict__ xs,
                        const float* __restrict__ bc, const float* __restrict__ Alog,
                        const float* __restrict__ Ds, const float* __restrict__ hin,
                        float* __restrict__ y) {
    int tid = blockIdx.x * blockDim.x + threadIdx.x;
    int n = tid & 7;
    int r = tid >> 3;
    int chunk = r & (NCHUNK - 1);
    int bd = r >> 7;
    int d = bd & (DI - 1);
    int b = bd >> 7;
    float An = -__expf(Alog[d * DST + n]);
    float Dd = Ds[d];
    const float* dp = delta + bd * LL + chunk * CHUNK;
    const float* xp = xs + bd * LL + chunk * CHUNK;
    const float* bp = bc + ((long)b * LL + chunk * CHUNK) * 16 + n;
    const float* cp = bp + 8;
    float h = hin[(bd * NCHUNK + chunk) * 8 + n];
    float* yp = y + bd * LL + chunk * CHUNK;
    #pragma unroll 2
    for (int t = 0; t < CHUNK; t++) {
        float dl = dp[t], xv = xp[t];
        float a = __expf(dl * An);
        float bx = dl * xv * bp[t * 16];
        h = a * h + bx;
        float yv = h * cp[t * 16];
        yv += __shfl_xor_sync(0xffffffffu, yv, 1);
        yv += __shfl_xor_sync(0xffffffffu, yv, 2);
        yv += __shfl_xor_sync(0xffffffffu, yv, 4);
        if (n == 0) yp[t] = yv + Dd * xv;
    }
}

// ---------------- K6a: LayerNorm(d=128) * gelu(z) ----------------
__global__ void k_lngelu(const float* __restrict__ y, const float* __restrict__ z,
                         const float* __restrict__ w, const float* __restrict__ bb,
                         float* __restrict__ tout) {
    __shared__ float sww[DI], sbb[DI];
    for (int i = threadIdx.x; i < DI; i += blockDim.x) { sww[i] = w[i]; sbb[i] = bb[i]; }
    __syncthreads();
    int px = blockIdx.x * blockDim.x + threadIdx.x;
    int b = blockIdx.y;
    if (px >= LL) return;
    const float* yp = y + b * DI * LL + px;
    float s = 0.f, s2 = 0.f;
    #pragma unroll 4
    for (int d = 0; d < DI; d++) { float v = yp[d * LL]; s += v; s2 += v * v; }
    float mu = s * (1.f / DI);
    float var = fmaxf(s2 * (1.f / DI) - mu * mu, 0.f);
    float rs = rsqrtf(var + 1e-5f);
    const float* zp = z + b * DI * LL + px;
    float* op = tout + b * DI * LL + px;
    #pragma unroll 4
    for (int d = 0; d < DI; d++) {
        float v = (yp[d * LL] - mu) * rs * sww[d] + sbb[d];
        op[d * LL] = v * gelu_f(zp[d * LL]);
    }
}

// ---------------- K9: depthwise 3x3 on h2 (no bias) + GLU gate ----------------
__global__ void k_dwconv_glu(const float* __restrict__ h2, const float* __restrict__ dw,
                             float* __restrict__ g) {
    int idx = blockIdx.x * blockDim.x + threadIdx.x;
    if (idx >= BATCH * HID * LL) return;
    int p = idx & (LL - 1);
    int o = (idx >> 14) % HID;
    int b = idx / (HID * LL);
    int h = p >> 7, w = p & 127;
    const float* inA = h2 + ((long)b * H2C + o) * LL;
    const float* inB = h2 + ((long)b * H2C + HID + o) * LL;
    const float* kA = dw + o * 9;
    const float* kB = dw + (HID + o) * 9;
    float a = 0.f, c2 = 0.f;
    #pragma unroll
    for (int dh = -1; dh <= 1; dh++) {
        int h2i = h + dh; if ((unsigned)h2i >= HH) continue;
        #pragma unroll
        for (int dwi = -1; dwi <= 1; dwi++) {
            int w2 = w + dwi; if ((unsigned)w2 >= WW) continue;
            float va = inA[h2i * WW + w2];
            float vb = inB[h2i * WW + w2];
            int ki = (dh + 1) * 3 + (dwi + 1);
            a  += va * kA[ki];
            c2 += vb * kB[ki];
        }
    }
    g[((long)b * HID + o) * LL + p] = gelu_f(a) * c2;
}

// ---------------- K11: per-patch 8x8 rfft2 * s -> irfft2, + residual ----------------
__global__ void __launch_bounds__(64) k_fft(const float* __restrict__ y2,
                                            const float* __restrict__ x2,
                                            const float* __restrict__ fp,
                                            float* __restrict__ out) {
    int tid = blockIdx.x * blockDim.x + threadIdx.x;
    int pw = tid & 15;
    int ph = (tid >> 4) & 15;
    int c = (tid >> 8) & 63;
    int b = tid >> 14;
    const float* base = y2 + ((long)b * CDIM + c) * LL + (ph * 8) * WW + pw * 8;
    float pr[8][8];
    #pragma unroll
    for (int i = 0; i < 8; i++) {
        float4 a0 = *(const float4*)(base + i * WW);
        float4 a1 = *(const float4*)(base + i * WW + 4);
        pr[i][0] = a0.x; pr[i][1] = a0.y; pr[i][2] = a0.z; pr[i][3] = a0.w;
        pr[i][4] = a1.x; pr[i][5] = a1.y; pr[i][6] = a1.z; pr[i][7] = a1.w;
    }

    float Gr[8][8], Gi[8][8];
    #pragma unroll
    for (int j = 0; j < 8; j++) {
        #pragma unroll
        for (int h = 0; h < 8; h++) {
            float sr = 0.f, si = 0.f;
            #pragma unroll
            for (int i = 0; i < 8; i++) {
                int k = (h * i) & 7;
                sr += pr[i][j] * C8[k];
                si -= pr[i][j] * S8[k];
            }
            Gr[h][j] = sr; Gi[h][j] = si;
        }
    }
    float Xr[8][5], Xi[8][5];
    const float* sp = fp + c * 40;
    #pragma unroll
    for (int h = 0; h < 8; h++) {
        #pragma unroll
        for (int w = 0; w < 5; w++) {
            float sr = 0.f, si = 0.f;
            #pragma unroll
            for (int j = 0; j < 8; j++) {
                int k = (w * j) & 7;
                float cr = C8[k], ci = -S8[k];
                sr += Gr[h][j] * cr - Gi[h][j] * ci;
                si += Gr[h][j] * ci + Gi[h][j] * cr;
            }
            float sc = sp[h * 5 + w];
            Xr[h][w] = sr * sc; Xi[h][w] = si * sc;
        }
    }
    float Kr[8][5], Ki[8][5];
    #pragma unroll
    for (int w = 0; w < 5; w++) {
        #pragma unroll
        for (int h = 0; h < 8; h++) {
            float sr = 0.f, si = 0.f;
            #pragma unroll
            for (int m = 0; m < 8; m++) {
                int k = (h * m) & 7;
                float cr = C8[k], ci = S8[k];
                sr += Xr[m][w] * cr - Xi[m][w] * ci;
                si += Xr[m][w] * ci + Xi[m][w] * cr;
            }
            Kr[h][w] = sr; Ki[h][w] = si;
        }
    }
    const float* xp = x2 + ((long)b * CDIM + c) * LL + (ph * 8) * WW + pw * 8;
    float* op = out + ((long)b * CDIM + c) * LL + (ph * 8) * WW + pw * 8;
    #pragma unroll
    for (int i = 0; i < 8; i++) {
        float res[8];
        #pragma unroll
        for (int j = 0; j < 8; j++) {
            float v = Kr[i][0] + ((j & 1) ? -Kr[i][4] : Kr[i][4]);
            #pragma unroll
            for (int w = 1; w < 4; w++) {
                int k = (w * j) & 7;
                v += 2.f * (Kr[i][w] * C8[k] - Ki[i][w] * S8[k]);
            }
            res[j] = v;
        }
        float4 r0 = *(const float4*)(xp + i * WW);
        float4 r1 = *(const float4*)(xp + i * WW + 4);
        float4 o0 = make_float4(r0.x + res[0] * (1.f/64.f), r0.y + res[1] * (1.f/64.f),
                                r0.z + res[2] * (1.f/64.f), r0.w + res[3] * (1.f/64.f));
        float4 o1 = make_float4(r1.x + res[4] * (1.f/64.f), r1.y + res[5] * (1.f/64.f),
                                r1.z + res[6] * (1.f/64.f), r1.w + res[7] * (1.f/64.f));
        *(float4*)(op + i * WW) = o0;
        *(float4*)(op + i * WW + 4) = o1;
    }
}

// ---------------- host launch ----------------
extern "C" void kernel_launch(void* const* d_in, const int* in_sizes, int n_in,
                              void* d_out, int out_size) {
    const float* x        = (const float*)d_in[0];
    const float* n1w      = (const float*)d_in[1];
    const float* n1b      = (const float*)d_in[2];
    const float* inprojw  = (const float*)d_in[3];
    const float* conv2dw  = (const float*)d_in[4];
    const float* conv2db  = (const float*)d_in[5];
    const float* xprojw   = (const float*)d_in[6];
    const float* xconvw   = (const float*)d_in[7];
    const float* xconvb   = (const float*)d_in[8];
    const float* dtpw     = (const float*)d_in[9];
    const float* dtpb     = (const float*)d_in[10];
    const float* Alogs    = (const float*)d_in[11];
    const float* Ds       = (const float*)d_in[12];
    const float* onw      = (const float*)d_in[13];
    const float* onb      = (const float*)d_in[14];
    const float* outprojw = (const float*)d_in[15];
    const float* n2w      = (const float*)d_in[16];
    const float* n2b      = (const float*)d_in[17];
    const float* pinw     = (const float*)d_in[18];
    const float* dww      = (const float*)d_in[19];
    const float* fftp     = (const float*)d_in[20];
    const float* poutw    = (const float*)d_in[21];
    float* out = (float*)d_out;

    float *xf, *xn, *xin, *z, *xs, *dbl0, *dtr, *bc, *delta, *y, *t, *x2, *h2, *g, *y2, *P, *S, *hin;
    cudaGetSymbolAddress((void**)&xf, g_xf);
    cudaGetSymbolAddress((void**)&xn, g_xn);
    cudaGetSymbolAddress((void**)&xin, g_xin);
    cudaGetSymbolAddress((void**)&z, g_z);
    cudaGetSymbolAddress((void**)&xs, g_xs);
    cudaGetSymbolAddress((void**)&dbl0, g_dbl0);
    cudaGetSymbolAddress((void**)&dtr, g_dtr);
    cudaGetSymbolAddress((void**)&bc, g_bc);
    cudaGetSymbolAddress((void**)&delta, g_delta);
    cudaGetSymbolAddress((void**)&y, g_y);
    cudaGetSymbolAddress((void**)&t, g_t);
    cudaGetSymbolAddress((void**)&x2, g_x2);
    cudaGetSymbolAddress((void**)&h2, g_h2);
    cudaGetSymbolAddress((void**)&g, g_g);
    cudaGetSymbolAddress((void**)&y2, g_y2);
    cudaGetSymbolAddress((void**)&P, g_P);
    cudaGetSymbolAddress((void**)&S, g_S);
    cudaGetSymbolAddress((void**)&hin, g_hin);

    dim3 px128(LL / 128, BATCH);

    k_flip_rms<<<px128, 128>>>(x, n1w, n1b, xf, xn);
    k_inproj<<<dim3(LL / 128, 4, BATCH), 256>>>(xn, inprojw, xin, z);
    k_dwconv2_gelu<<<(BATCH * DI * LL) / 256, 256>>>(xin, conv2dw, conv2db, xs);
    k_xproj<<<dim3(LL / 256, BATCH), 128>>>(xs, xprojw, dbl0);
    k_dwconv1<<<(BATCH * NCHC * LL) / 256, 256>>>(dbl0, xconvw, xconvb, dtr, bc);
    k_delta<<<px128, 128>>>(dtr, dtpw, dtpb, delta);
    k_scanA<<<(BATCH * DI * NCHUNK * DST) / 256, 256>>>(delta, xs, bc, Alogs, P, S);
    k_scanB<<<(BATCH * DI * DST) / 256, 256>>>(P, S, hin);
    k_scanC<<<(BATCH * DI * NCHUNK * DST) / 256, 256>>>(delta, xs, bc, Alogs, Ds, hin, y);
    k_lngelu<<<px128, 128>>>(y, z, onw, onb, t);
    k_outproj<<<dim3(LL / 128, 1, BATCH), 256>>>(t, outprojw, xf, x2);
    k_rms<<<px128, 128>>>(x2, n2w, n2b, xn);
    k_pin<<<dim3(LL / 128, 6, BATCH), 256>>>(xn, pinw, h2);
    k_dwconv_glu<<<(BATCH * HID * LL) / 256, 256>>>(h2, dww, g);
    k_pout<<<dim3(LL / 128, 1, BATCH), 256>>>(g, poutw, y2);
    k_fft<<<(BATCH * CDIM * 16 * 16) / 64, 64>>>(y2, x2, fftp, out);

    (void)in_sizes; (void)n_in; (void)out_size;
}

// round 5
// speedup vs baseline: 1.4713x; 1.1479x over previous
#include <cuda_runtime.h>
#include <math.h>

// ---------------- problem constants ----------------
#define BATCH 2
#define CDIM 64
#define DI   128          // D_INNER
#define HH   128
#define WW   128
#define LL   (HH*WW)      // 16384
#define NCHC 20           // DT_RANK + 2*D_STATE
#define DTR  4
#define DST  8
#define HID  192
#define H2C  384
#define CHUNK   128
#define NCHUNK  (LL/CHUNK)   // 128

// ---------------- scratch (device globals; no allocation allowed) ----------------
__device__ float g_xf   [BATCH*CDIM*LL];
__device__ float g_xn   [BATCH*CDIM*LL];
__device__ float g_xin  [BATCH*DI*LL];
__device__ float g_z    [BATCH*DI*LL];
__device__ float g_xs   [BATCH*DI*LL];
__device__ float g_dbl0 [BATCH*NCHC*LL];
__device__ float g_dtr  [BATCH*DTR*LL];
__device__ float g_bc   [BATCH*LL*16];          // [b][p][0..7]=B, [8..15]=C
__device__ float g_delta[BATCH*DI*LL];
__device__ float g_y    [BATCH*DI*LL];
__device__ float g_t    [BATCH*DI*LL];
__device__ float g_x2   [BATCH*CDIM*LL];
__device__ float g_h2   [BATCH*H2C*LL];
__device__ float g_g    [BATCH*HID*LL];
__device__ float g_y2   [BATCH*CDIM*LL];
__device__ float g_P    [BATCH*DI*NCHUNK*DST];
__device__ float g_S    [BATCH*DI*NCHUNK*DST];
__device__ float g_hin  [BATCH*DI*NCHUNK*DST];
__device__ float g_K    [CDIM*64];              // per-channel 8x8 circular-conv kernel

// twiddles for 8-point DFT
__device__ __constant__ float C8[8] = {1.f, 0.70710678118654752f, 0.f, -0.70710678118654752f,
                                      -1.f, -0.70710678118654752f, 0.f, 0.70710678118654752f};
__device__ __constant__ float S8[8] = {0.f, 0.70710678118654752f, 1.f, 0.70710678118654752f,
                                       0.f, -0.70710678118654752f, -1.f, -0.70710678118654752f};

__device__ __forceinline__ float gelu_f(float x) {
    return 0.5f * x * (1.0f + erff(x * 0.70710678118654752f));
}
__device__ __forceinline__ float softplus_f(float x) {
    return (x > 20.f) ? x : log1pf(__expf(x));
}

// =====================================================================
// Tiled GEMM core: 64 outs x 128 px tiles, 256 threads, 32 acc/thread.
// =====================================================================
template<int K>
__device__ __forceinline__ void gemm_tile_core(const float* __restrict__ Xb,
                                               const float* __restrict__ Wo,
                                               float* s_x, float* s_w,
                                               float4 (&acc)[8]) {
    const int t  = threadIdx.x;
    const int tx = t & 31;
    const int ty = t >> 5;
    #pragma unroll
    for (int j = 0; j < 8; j++) acc[j] = make_float4(0.f, 0.f, 0.f, 0.f);

    for (int kc = 0; kc < K; kc += 64) {
        __syncthreads();
        {
            const int col4 = t & 31;
            const int c0   = t >> 5;
            #pragma unroll
            for (int r = 0; r < 8; r++) {
                int c = c0 + r * 8;
                *(float4*)(s_x + c * 128 + col4 * 4) =
                    *(const float4*)(Xb + (kc + c) * LL + col4 * 4);
            }
        }
        {
            const int o   = t >> 2;
            const int k4b = t & 3;
            #pragma unroll
            for (int r = 0; r < 4; r++) {
                int k4 = k4b + r * 4;
                float4 v = *(const float4*)(Wo + o * K + kc + k4 * 4);
                s_w[(k4 * 4 + 0) * 64 + o] = v.x;
                s_w[(k4 * 4 + 1) * 64 + o] = v.y;
                s_w[(k4 * 4 + 2) * 64 + o] = v.z;
                s_w[(k4 * 4 + 3) * 64 + o] = v.w;
            }
        }
        __syncthreads();
        #pragma unroll 16
        for (int c = 0; c < 64; c++) {
            float4 xv = *(const float4*)(s_x + c * 128 + tx * 4);
            float4 wa = *(const float4*)(s_w + c * 64 + ty * 8);
            float4 wb = *(const float4*)(s_w + c * 64 + ty * 8 + 4);
            acc[0].x += wa.x * xv.x; acc[0].y += wa.x * xv.y; acc[0].z += wa.x * xv.z; acc[0].w += wa.x * xv.w;
            acc[1].x += wa.y * xv.x; acc[1].y += wa.y * xv.y; acc[1].z += wa.y * xv.z; acc[1].w += wa.y * xv.w;
            acc[2].x += wa.z * xv.x; acc[2].y += wa.z * xv.y; acc[2].z += wa.z * xv.z; acc[2].w += wa.z * xv.w;
            acc[3].x += wa.w * xv.x; acc[3].y += wa.w * xv.y; acc[3].z += wa.w * xv.z; acc[3].w += wa.w * xv.w;
            acc[4].x += wb.x * xv.x; acc[4].y += wb.x * xv.y; acc[4].z += wb.x * xv.z; acc[4].w += wb.x * xv.w;
            acc[5].x += wb.y * xv.x; acc[5].y += wb.y * xv.y; acc[5].z += wb.y * xv.z; acc[5].w += wb.y * xv.w;
            acc[6].x += wb.z * xv.x; acc[6].y += wb.z * xv.y; acc[6].z += wb.z * xv.z; acc[6].w += wb.z * xv.w;
            acc[7].x += wb.w * xv.x; acc[7].y += wb.w * xv.y; acc[7].z += wb.w * xv.z; acc[7].w += wb.w * xv.w;
        }
    }
}

// ---------------- K1: in_proj 64->256, split into xin / z ----------------
__global__ void __launch_bounds__(256) k_inproj(const float* __restrict__ xn,
                                                const float* __restrict__ W,
                                                float* __restrict__ xin,
                                                float* __restrict__ z) {
    __shared__ float s_x[64 * 128];
    __shared__ float s_w[64 * 64];
    const int b = blockIdx.z, oz = blockIdx.y, p0 = blockIdx.x * 128;
    float4 acc[8];
    gemm_tile_core<64>(xn + b * CDIM * LL + p0, W + oz * 64 * 64, s_x, s_w, acc);
    const int tx = threadIdx.x & 31, ty = threadIdx.x >> 5;
    const int og = oz * 64 + ty * 8;
    float* dst = (og < DI) ? (xin + (long)b * DI * LL + og * LL)
                           : (z + (long)b * DI * LL + (og - DI) * LL);
    #pragma unroll
    for (int j = 0; j < 8; j++)
        *(float4*)(dst + j * LL + p0 + tx * 4) = acc[j];
}

// ---------------- K8: pin 64->384 ----------------
__global__ void __launch_bounds__(256) k_pin(const float* __restrict__ xn,
                                             const float* __restrict__ W,
                                             float* __restrict__ h2) {
    __shared__ float s_x[64 * 128];
    __shared__ float s_w[64 * 64];
    const int b = blockIdx.z, oz = blockIdx.y, p0 = blockIdx.x * 128;
    float4 acc[8];
    gemm_tile_core<64>(xn + b * CDIM * LL + p0, W + oz * 64 * 64, s_x, s_w, acc);
    const int tx = threadIdx.x & 31, ty = threadIdx.x >> 5;
    const int og = oz * 64 + ty * 8;
    float* dst = h2 + (long)b * H2C * LL + (long)og * LL;
    #pragma unroll
    for (int j = 0; j < 8; j++)
        *(float4*)(dst + j * LL + p0 + tx * 4) = acc[j];
}

// ---------------- K6b: out_proj 128->64 + residual + FUSED rms(norm2) ----------------
__global__ void __launch_bounds__(256) k_outproj(const float* __restrict__ tin,
                                                 const float* __restrict__ W,
                                                 const float* __restrict__ xf,
                                                 const float* __restrict__ n2w,
                                                 const float* __restrict__ n2b,
                                                 float* __restrict__ x2,
                                                 float* __restrict__ xn) {
    __shared__ float s_x[64 * 128];
    __shared__ float s_w[64 * 64];
    const int b = blockIdx.z, p0 = blockIdx.x * 128;
    float4 acc[8];
    gemm_tile_core<128>(tin + (long)b * DI * LL + p0, W, s_x, s_w, acc);
    const int t = threadIdx.x;
    const int tx = t & 31, ty = t >> 5;
    const float* xp = xf + (long)b * CDIM * LL + (ty * 8) * LL + p0 + tx * 4;
    float* dst = x2 + (long)b * CDIM * LL + (ty * 8) * LL + p0 + tx * 4;
    float4 ssq = make_float4(0.f, 0.f, 0.f, 0.f);
    #pragma unroll
    for (int j = 0; j < 8; j++) {
        float4 r = *(const float4*)(xp + j * LL);
        acc[j].x += r.x; acc[j].y += r.y; acc[j].z += r.z; acc[j].w += r.w;
        *(float4*)(dst + j * LL) = acc[j];
        ssq.x += acc[j].x * acc[j].x; ssq.y += acc[j].y * acc[j].y;
        ssq.z += acc[j].z * acc[j].z; ssq.w += acc[j].w * acc[j].w;
    }
    // rms over 64 channels: reduce across the 8 ty-groups via smem (reuse s_w)
    __syncthreads();                 // everyone done reading s_w
    float* s_red = s_w;              // [8][128]
    float* s_rs  = s_w + 1024;       // [128]
    *(float4*)(s_red + ty * 128 + tx * 4) = ssq;
    __syncthreads();
    if (t < 128) {
        float s = 0.f;
        #pragma unroll
        for (int g = 0; g < 8; g++) s += s_red[g * 128 + t];
        s_rs[t] = rsqrtf(s * (1.0f / CDIM) + 1e-6f);
    }
    __syncthreads();
    float4 rs4 = *(const float4*)(s_rs + tx * 4);
    float* np = xn + (long)b * CDIM * LL + (ty * 8) * LL + p0 + tx * 4;
    #pragma unroll
    for (int j = 0; j < 8; j++) {
        int og = ty * 8 + j;
        float wj = n2w[og], bj = n2b[og];
        float4 o;
        o.x = acc[j].x * rs4.x * wj + bj;
        o.y = acc[j].y * rs4.y * wj + bj;
        o.z = acc[j].z * rs4.z * wj + bj;
        o.w = acc[j].w * rs4.w * wj + bj;
        *(float4*)(np + j * LL) = o;
    }
}

// ---------------- K10: pout 192->64 ----------------
__global__ void __launch_bounds__(256) k_pout(const float* __restrict__ gg,
                                              const float* __restrict__ W,
                                              float* __restrict__ y2) {
    __shared__ float s_x[64 * 128];
    __shared__ float s_w[64 * 64];
    const int b = blockIdx.z, p0 = blockIdx.x * 128;
    float4 acc[8];
    gemm_tile_core<192>(gg + (long)b * HID * LL + p0, W, s_x, s_w, acc);
    const int tx = threadIdx.x & 31, ty = threadIdx.x >> 5;
    float* dst = y2 + (long)b * CDIM * LL + (ty * 8) * LL + p0 + tx * 4;
    #pragma unroll
    for (int j = 0; j < 8; j++)
        *(float4*)(dst + j * LL) = acc[j];
}

// ---------------- K3a: x_proj 128->20, v2: 64px tiles, K split 4 ways ----------------
__global__ void __launch_bounds__(256) k_xproj(const float* __restrict__ xs,
                                               const float* __restrict__ Wg,
                                               float* __restrict__ out) {
    __shared__ float s_x[DI * 64];    // [ch][px] 32KB (reused as reduction buffer)
    __shared__ float s_w[DI * NCHC];  // transposed [d][c] 10KB
    const int t = threadIdx.x;
    const int b = blockIdx.y, p0 = blockIdx.x * 64;
    for (int i = t; i < DI * NCHC; i += 256) {
        int c = i % NCHC, d = i / NCHC;
        s_w[i] = Wg[c * DI + d];
    }
    const float* Xb = xs + (long)b * DI * LL + p0;
    for (int i = t; i < DI * 16; i += 256) {
        int ch = i >> 4, c4 = i & 15;
        *(float4*)(s_x + ch * 64 + c4 * 4) = *(const float4*)(Xb + ch * LL + c4 * 4);
    }
    __syncthreads();
    const int px = t & 63, kg = t >> 6;   // kg in [0,4): channels kg*32..+31
    float acc[NCHC];
    #pragma unroll
    for (int c = 0; c < NCHC; c++) acc[c] = 0.f;
    #pragma unroll 8
    for (int c = 0; c < 32; c++) {
        int ch = kg * 32 + c;
        float xv = s_x[ch * 64 + px];
        const float* wr = s_w + ch * NCHC;
        #pragma unroll
        for (int i = 0; i < 5; i++) {
            float4 w4 = *(const float4*)(wr + i * 4);
            acc[4*i+0] += w4.x * xv; acc[4*i+1] += w4.y * xv;
            acc[4*i+2] += w4.z * xv; acc[4*i+3] += w4.w * xv;
        }
    }
    __syncthreads();
    float* s_r = s_x;   // [kg][o][px] : 4*20*64 floats = 20KB
    #pragma unroll
    for (int o = 0; o < NCHC; o++) s_r[(kg * NCHC + o) * 64 + px] = acc[o];
    __syncthreads();
    #pragma unroll
    for (int q = 0; q < 5; q++) {
        int idx = t + q * 256;
        int o = idx >> 6, px2 = idx & 63;
        float sum = s_r[(0 * NCHC + o) * 64 + px2] + s_r[(1 * NCHC + o) * 64 + px2]
                  + s_r[(2 * NCHC + o) * 64 + px2] + s_r[(3 * NCHC + o) * 64 + px2];
        out[(long)b * NCHC * LL + o * LL + p0 + px2] = sum;
    }
}

// ---------------- K0: flip + rmsnorm(norm1), keep flipped copy ----------------
__global__ void k_flip_rms(const float* __restrict__ x, const float* __restrict__ w,
                           const float* __restrict__ bb, float* __restrict__ xf,
                           float* __restrict__ xn) {
    int p = blockIdx.x * blockDim.x + threadIdx.x;
    int b = blockIdx.y;
    if (p >= LL) return;
    float v[CDIM];
    float ss = 0.f;
    int src = b * CDIM * LL + (LL - 1 - p);
    #pragma unroll
    for (int c = 0; c < CDIM; c++) { float t = x[src + c * LL]; v[c] = t; ss += t * t; }
    float rs = rsqrtf(ss * (1.0f / CDIM) + 1e-6f);
    int dst = b * CDIM * LL + p;
    #pragma unroll
    for (int c = 0; c < CDIM; c++) {
        xf[dst + c * LL] = v[c];
        xn[dst + c * LL] = v[c] * rs * w[c] + bb[c];
    }
}

// ---------------- K2: depthwise 3x3 + bias + gelu, 4px/thread ----------------
__global__ void __launch_bounds__(256) k_dwconv2_gelu(const float* __restrict__ xin,
                                                      const float* __restrict__ cw,
                                                      const float* __restrict__ cb,
                                                      float* __restrict__ xs) {
    int q = blockIdx.x * blockDim.x + threadIdx.x;        // BATCH*DI*LL/4
    int pq = q & (LL / 4 - 1);
    int d = (q >> 12) & (DI - 1);
    int b = q >> 19;
    int p = pq * 4;
    int h = p >> 7, w0 = p & 127;
    const float* in = xin + ((long)b * DI + d) * LL;
    const float* k = cw + d * 9;
    float bias = cb[d];
    float a0 = bias, a1 = bias, a2 = bias, a3 = bias;
    #pragma unroll
    for (int dh = -1; dh <= 1; dh++) {
        int h2 = h + dh; if ((unsigned)h2 >= HH) continue;
        const float* row = in + h2 * WW;
        float k0 = k[(dh + 1) * 3], k1 = k[(dh + 1) * 3 + 1], k2 = k[(dh + 1) * 3 + 2];
        float l = (w0 > 0) ? row[w0 - 1] : 0.f;
        float4 m = *(const float4*)(row + w0);
        float r = (w0 + 4 < WW) ? row[w0 + 4] : 0.f;
        a0 += l   * k0 + m.x * k1 + m.y * k2;
        a1 += m.x * k0 + m.y * k1 + m.z * k2;
        a2 += m.y * k0 + m.z * k1 + m.w * k2;
        a3 += m.z * k0 + m.w * k1 + r   * k2;
    }
    float4 o = make_float4(gelu_f(a0), gelu_f(a1), gelu_f(a2), gelu_f(a3));
    *(float4*)(xs + ((long)b * DI + d) * LL + p) = o;
}

// ---------------- K3b: depthwise 1d conv (k=7, pad 3) + bias ----------------
__global__ void k_dwconv1(const float* __restrict__ in, const float* __restrict__ cw,
                          const float* __restrict__ cb, float* __restrict__ dtr,
                          float* __restrict__ bc) {
    int idx = blockIdx.x * blockDim.x + threadIdx.x;
    if (idx >= BATCH * NCHC * LL) return;
    int p = idx % LL;
    int c = (idx / LL) % NCHC;
    int b = idx / (LL * NCHC);
    const float* ip = in + (b * NCHC + c) * LL;
    const float* k = cw + c * 7;
    float acc = cb[c];
    #pragma unroll
    for (int t = -3; t <= 3; t++) {
        int pp = p + t;
        if ((unsigned)pp < LL) acc += ip[pp] * k[t + 3];
    }
    if (c < DTR) dtr[(b * DTR + c) * LL + p] = acc;
    else         bc[((long)b * LL + p) * 16 + (c - DTR)] = acc;
}

// ---------------- K4: dt projection + softplus -> delta ----------------
__global__ void k_delta(const float* __restrict__ dtr, const float* __restrict__ dtw,
                        const float* __restrict__ dtb, float* __restrict__ delta) {
    __shared__ float sw[DI * 4];
    __shared__ float sb[DI];
    for (int i = threadIdx.x; i < DI * 4; i += blockDim.x) sw[i] = dtw[i];
    for (int i = threadIdx.x; i < DI; i += blockDim.x) sb[i] = dtb[i];
    __syncthreads();
    int px = blockIdx.x * blockDim.x + threadIdx.x;
    int b = blockIdx.y;
    if (px >= LL) return;
    const float* rp = dtr + b * DTR * LL + px;
    float r0 = rp[0], r1 = rp[LL], r2 = rp[2 * LL], r3 = rp[3 * LL];
    float* op = delta + b * DI * LL + px;
    #pragma unroll 4
    for (int d = 0; d < DI; d++) {
        float4 w4 = ((const float4*)sw)[d];
        float s = r0 * w4.x + r1 * w4.y + r2 * w4.z + r3 * w4.w + sb[d];
        op[d * LL] = softplus_f(s);
    }
}

// ---------------- K5a: chunked scan pass A (local P, S) ----------------
__global__ void k_scanA(const float* __restrict__ delta, const float* __restrict__ xs,
                        const float* __restrict__ bc, const float* __restrict__ Alog,
                        float* __restrict__ P, float* __restrict__ S) {
    int tid = blockIdx.x * blockDim.x + threadIdx.x;
    int n = tid & 7;
    int r = tid >> 3;
    int chunk = r & (NCHUNK - 1);
    int bd = r >> 7;
    int d = bd & (DI - 1);
    float An = -__expf(Alog[d * DST + n]);
    int b = bd >> 7;
    const float* dp = delta + bd * LL + chunk * CHUNK;
    const float* xp = xs + bd * LL + chunk * CHUNK;
    const float* bp = bc + ((long)b * LL + chunk * CHUNK) * 16 + n;
    float Pv = 1.f, Sv = 0.f;
    #pragma unroll 4
    for (int t = 0; t < CHUNK; t++) {
        float dl = dp[t], xv = xp[t];
        float a = __expf(dl * An);
        float bx = dl * xv * bp[t * 16];
        Pv *= a;
        Sv = a * Sv + bx;
    }
    int o = (bd * NCHUNK + chunk) * 8 + n;
    P[o] = Pv; S[o] = Sv;
}

// ---------------- K5b: scan across chunks ----------------
__global__ void k_scanB(const float* __restrict__ P, const float* __restrict__ S,
                        float* __restrict__ hin) {
    int tid = blockIdx.x * blockDim.x + threadIdx.x;
    int n = tid & 7;
    int bd = tid >> 3;
    float h = 0.f;
    int base = bd * NCHUNK * 8 + n;
    for (int c = 0; c < NCHUNK; c++) {
        int o = base + c * 8;
        hin[o] = h;
        h = P[o] * h + S[o];
    }
}

// ---------------- K5c: pass C — recompute with true h_in, emit y ----------------
__global__ void k_scanC(const float* __restrict__ delta, const float* __restrict__ xs,
                        const float* __restrict__ bc, const float* __restrict__ Alog,
                        const float* __restrict__ Ds, const float* __restrict__ hin,
                        float* __restrict__ y) {
    int tid = blockIdx.x * blockDim.x + threadIdx.x;
    int n = tid & 7;
    int r = tid >> 3;
    int chunk = r & (NCHUNK - 1);
    int bd = r >> 7;
    int d = bd & (DI - 1);
    int b = bd >> 7;
    float An = -__expf(Alog[d * DST + n]);
    float Dd = Ds[d];
    const float* dp = delta + bd * LL + chunk * CHUNK;
    const float* xp = xs + bd * LL + chunk * CHUNK;
    const float* bp = bc + ((long)b * LL + chunk * CHUNK) * 16 + n;
    const float* cp = bp + 8;
    float h = hin[(bd * NCHUNK + chunk) * 8 + n];
    float* yp = y + bd * LL + chunk * CHUNK;
    #pragma unroll 2
    for (int t = 0; t < CHUNK; t++) {
        float dl = dp[t], xv = xp[t];
        float a = __expf(dl * An);
        float bx = dl * xv * bp[t * 16];
        h = a * h + bx;
        float yv = h * cp[t * 16];
        yv += __shfl_xor_sync(0xffffffffu, yv, 1);
        yv += __shfl_xor_sync(0xffffffffu, yv, 2);
        yv += __shfl_xor_sync(0xffffffffu, yv, 4);
        if (n == 0) yp[t] = yv + Dd * xv;
    }
}

// ---------------- K6a: LayerNorm(d=128) * gelu(z), 2 threads/px ----------------
__global__ void __launch_bounds__(256) k_lngelu(const float* __restrict__ y,
                                                const float* __restrict__ z,
                                                const float* __restrict__ w,
                                                const float* __restrict__ bb,
                                                float* __restrict__ tout) {
    __shared__ float sww[DI], sbb[DI];
    __shared__ float s_s[256], s_s2[256];
    int t = threadIdx.x;
    if (t < DI) { sww[t] = w[t]; sbb[t] = bb[t]; }
    int px = blockIdx.x * 128 + (t & 127);
    int half = t >> 7;                   // 0: d 0..63, 1: d 64..127
    int b = blockIdx.y;
    const float* yp = y + (long)b * DI * LL + half * 64 * LL + px;
    float v[64];
    float s = 0.f, s2 = 0.f;
    #pragma unroll 8
    for (int d = 0; d < 64; d++) { float u = yp[d * LL]; v[d] = u; s += u; s2 += u * u; }
    s_s[t] = s; s_s2[t] = s2;
    __syncthreads();
    int other = t ^ 128;
    float S = s_s[t] + s_s[other];
    float S2 = s_s2[t] + s_s2[other];
    float mu = S * (1.f / DI);
    float var = fmaxf(S2 * (1.f / DI) - mu * mu, 0.f);
    float rs = rsqrtf(var + 1e-5f);
    const float* zp = z + (long)b * DI * LL + half * 64 * LL + px;
    float* op = tout + (long)b * DI * LL + half * 64 * LL + px;
    #pragma unroll 8
    for (int d = 0; d < 64; d++) {
        float val = (v[d] - mu) * rs * sww[half * 64 + d] + sbb[half * 64 + d];
        op[d * LL] = val * gelu_f(zp[d * LL]);
    }
}

// ---------------- K9: depthwise 3x3 + GLU gate, 4px/thread ----------------
__global__ void __launch_bounds__(256) k_dwconv_glu(const float* __restrict__ h2,
                                                    const float* __restrict__ dw,
                                                    float* __restrict__ g) {
    int q = blockIdx.x * blockDim.x + threadIdx.x;        // BATCH*HID*LL/4
    int pq = q & (LL / 4 - 1);
    int o = (q >> 12) % HID;
    int b = q / (HID * (LL / 4));
    int p = pq * 4;
    int h = p >> 7, w0 = p & 127;
    const float* inA = h2 + ((long)b * H2C + o) * LL;
    const float* inB = h2 + ((long)b * H2C + HID + o) * LL;
    const float* kA = dw + o * 9;
    const float* kB = dw + (HID + o) * 9;
    float a0 = 0.f, a1 = 0.f, a2 = 0.f, a3 = 0.f;
    float c0 = 0.f, c1 = 0.f, c2 = 0.f, c3 = 0.f;
    #pragma unroll
    for (int dh = -1; dh <= 1; dh++) {
        int h2i = h + dh; if ((unsigned)h2i >= HH) continue;
        const float* rowA = inA + h2i * WW;
        const float* rowB = inB + h2i * WW;
        float ka0 = kA[(dh+1)*3], ka1 = kA[(dh+1)*3+1], ka2 = kA[(dh+1)*3+2];
        float kb0 = kB[(dh+1)*3], kb1 = kB[(dh+1)*3+1], kb2 = kB[(dh+1)*3+2];
        float la = (w0 > 0) ? rowA[w0 - 1] : 0.f;
        float lb = (w0 > 0) ? rowB[w0 - 1] : 0.f;
        float4 ma = *(const float4*)(rowA + w0);
        float4 mb = *(const float4*)(rowB + w0);
        float ra = (w0 + 4 < WW) ? rowA[w0 + 4] : 0.f;
        float rb = (w0 + 4 < WW) ? rowB[w0 + 4] : 0.f;
        a0 += la   * ka0 + ma.x * ka1 + ma.y * ka2;
        a1 += ma.x * ka0 + ma.y * ka1 + ma.z * ka2;
        a2 += ma.y * ka0 + ma.z * ka1 + ma.w * ka2;
        a3 += ma.z * ka0 + ma.w * ka1 + ra   * ka2;
        c0 += lb   * kb0 + mb.x * kb1 + mb.y * kb2;
        c1 += mb.x * kb0 + mb.y * kb1 + mb.z * kb2;
        c2 += mb.y * kb0 + mb.z * kb1 + mb.w * kb2;
        c3 += mb.z * kb0 + mb.w * kb1 + rb   * kb2;
    }
    float4 out4 = make_float4(gelu_f(a0) * c0, gelu_f(a1) * c1,
                              gelu_f(a2) * c2, gelu_f(a3) * c3);
    *(float4*)(g + ((long)b * HID + o) * LL + p) = out4;
}

// ---------------- K11a: precompute per-channel circular-conv kernel from fft_p ----------------
__global__ void k_fftker(const float* __restrict__ fp, float* __restrict__ Kout) {
    int c = threadIdx.x;
    if (c >= CDIM) return;
    const float* sp = fp + c * 40;
    float Xr[8][5];
    #pragma unroll
    for (int h = 0; h < 8; h++)
        #pragma unroll
        for (int w = 0; w < 5; w++) Xr[h][w] = sp[h * 5 + w];
    float Kr[8][5], Ki[8][5];
    #pragma unroll
    for (int w = 0; w < 5; w++) {
        #pragma unroll
        for (int h = 0; h < 8; h++) {
            float sr = 0.f, si = 0.f;
            #pragma unroll
            for (int m = 0; m < 8; m++) {
                int k = (h * m) & 7;
                sr += Xr[m][w] * C8[k];
                si += Xr[m][w] * S8[k];
            }
            Kr[h][w] = sr; Ki[h][w] = si;
        }
    }
    #pragma unroll
    for (int i = 0; i < 8; i++) {
        #pragma unroll
        for (int j = 0; j < 8; j++) {
            float v = Kr[i][0] + ((j & 1) ? -Kr[i][4] : Kr[i][4]);
            #pragma unroll
            for (int w = 1; w < 4; w++) {
                int k = (w * j) & 7;
                v += 2.f * (Kr[i][w] * C8[k] - Ki[i][w] * S8[k]);
            }
            Kout[c * 64 + i * 8 + j] = v * (1.f / 64.f);
        }
    }
}

// ---------------- K11b: per-patch circular conv with K_c + residual ----------------
__global__ void __launch_bounds__(128) k_fft(const float* __restrict__ y2,
                                             const float* __restrict__ x2,
                                             const float* __restrict__ Kg,
                                             float* __restrict__ out) {
    __shared__ float s_P[8 * 128];
    __shared__ float s_K[64];
    int blk = blockIdx.x;
    int ph = blk & 15;
    int bc = blk >> 4;        // b*CDIM + c
    int c = bc & (CDIM - 1);
    const float* base = y2 + (long)bc * LL + (ph * 8) * WW;
    int t = threadIdx.x;
    for (int i = t; i < 256; i += 128) {
        int r = i >> 5, c4 = i & 31;
        *(float4*)(s_P + r * 128 + c4 * 4) = *(const float4*)(base + r * WW + c4 * 4);
    }
    if (t < 64) s_K[t] = Kg[c * 64 + t];
    __syncthreads();
    int pw = t & 15;
    int i = t >> 4;
    float acc[8] = {0.f, 0.f, 0.f, 0.f, 0.f, 0.f, 0.f, 0.f};
    #pragma unroll
    for (int a = 0; a < 8; a++) {
        float4 p0 = *(const float4*)(s_P + a * 128 + pw * 8);
        float4 p1 = *(const float4*)(s_P + a * 128 + pw * 8 + 4);
        float pa[8] = {p0.x, p0.y, p0.z, p0.w, p1.x, p1.y, p1.z, p1.w};
        int krow = (i - a) & 7;
        float4 k0 = *(const float4*)(s_K + krow * 8);
        float4 k1 = *(const float4*)(s_K + krow * 8 + 4);
        float kr[8] = {k0.x, k0.y, k0.z, k0.w, k1.x, k1.y, k1.z, k1.w};
        #pragma unroll
        for (int bb = 0; bb < 8; bb++) {
            #pragma unroll
            for (int j = 0; j < 8; j++)
                acc[j] += pa[bb] * kr[(j - bb) & 7];
        }
    }
    const float* xp = x2 + (long)bc * LL + (ph * 8 + i) * WW + pw * 8;
    float* op = out + (long)bc * LL + (ph * 8 + i) * WW + pw * 8;
    float4 r0 = *(const float4*)(xp);
    float4 r1 = *(const float4*)(xp + 4);
    float4 o0 = make_float4(acc[0] + r0.x, acc[1] + r0.y, acc[2] + r0.z, acc[3] + r0.w);
    float4 o1 = make_float4(acc[4] + r1.x, acc[5] + r1.y, acc[6] + r1.z, acc[7] + r1.w);
    *(float4*)(op) = o0;
    *(float4*)(op + 4) = o1;
}

// ---------------- host launch ----------------
extern "C" void kernel_launch(void* const* d_in, const int* in_sizes, int n_in,
                              void* d_out, int out_size) {
    const float* x        = (const float*)d_in[0];
    const float* n1w      = (const float*)d_in[1];
    const float* n1b      = (const float*)d_in[2];
    const float* inprojw  = (const float*)d_in[3];
    const float* conv2dw  = (const float*)d_in[4];
    const float* conv2db  = (const float*)d_in[5];
    const float* xprojw   = (const float*)d_in[6];
    const float* xconvw   = (const float*)d_in[7];
    const float* xconvb   = (const float*)d_in[8];
    const float* dtpw     = (const float*)d_in[9];
    const float* dtpb     = (const float*)d_in[10];
    const float* Alogs    = (const float*)d_in[11];
    const float* Ds       = (const float*)d_in[12];
    const float* onw      = (const float*)d_in[13];
    const float* onb      = (const float*)d_in[14];
    const float* outprojw = (const float*)d_in[15];
    const float* n2w      = (const float*)d_in[16];
    const float* n2b      = (const float*)d_in[17];
    const float* pinw     = (const float*)d_in[18];
    const float* dww      = (const float*)d_in[19];
    const float* fftp     = (const float*)d_in[20];
    const float* poutw    = (const float*)d_in[21];
    float* out = (float*)d_out;

    float *xf, *xn, *xin, *z, *xs, *dbl0, *dtr, *bc, *delta, *y, *t, *x2, *h2, *g, *y2, *P, *S, *hin, *Kc;
    cudaGetSymbolAddress((void**)&xf, g_xf);
    cudaGetSymbolAddress((void**)&xn, g_xn);
    cudaGetSymbolAddress((void**)&xin, g_xin);
    cudaGetSymbolAddress((void**)&z, g_z);
    cudaGetSymbolAddress((void**)&xs, g_xs);
    cudaGetSymbolAddress((void**)&dbl0, g_dbl0);
    cudaGetSymbolAddress((void**)&dtr, g_dtr);
    cudaGetSymbolAddress((void**)&bc, g_bc);
    cudaGetSymbolAddress((void**)&delta, g_delta);
    cudaGetSymbolAddress((void**)&y, g_y);
    cudaGetSymbolAddress((void**)&t, g_t);
    cudaGetSymbolAddress((void**)&x2, g_x2);
    cudaGetSymbolAddress((void**)&h2, g_h2);
    cudaGetSymbolAddress((void**)&g, g_g);
    cudaGetSymbolAddress((void**)&y2, g_y2);
    cudaGetSymbolAddress((void**)&P, g_P);
    cudaGetSymbolAddress((void**)&S, g_S);
    cudaGetSymbolAddress((void**)&hin, g_hin);
    cudaGetSymbolAddress((void**)&Kc, g_K);

    dim3 px128(LL / 128, BATCH);

    k_fftker<<<1, 64>>>(fftp, Kc);   // independent; fires early
    k_flip_rms<<<px128, 128>>>(x, n1w, n1b, xf, xn);
    k_inproj<<<dim3(LL / 128, 4, BATCH), 256>>>(xn, inprojw, xin, z);
    k_dwconv2_gelu<<<(BATCH * DI * LL / 4) / 256, 256>>>(xin, conv2dw, conv2db, xs);
    k_xproj<<<dim3(LL / 64, BATCH), 256>>>(xs, xprojw, dbl0);
    k_dwconv1<<<(BATCH * NCHC * LL) / 256, 256>>>(dbl0, xconvw, xconvb, dtr, bc);
    k_delta<<<px128, 128>>>(dtr, dtpw, dtpb, delta);
    k_scanA<<<(BATCH * DI * NCHUNK * DST) / 256, 256>>>(delta, xs, bc, Alogs, P, S);
    k_scanB<<<(BATCH * DI * DST) / 256, 256>>>(P, S, hin);
    k_scanC<<<(BATCH * DI * NCHUNK * DST) / 256, 256>>>(delta, xs, bc, Alogs, Ds, hin, y);
    k_lngelu<<<dim3(LL / 128, BATCH), 256>>>(y, z, onw, onb, t);
    k_outproj<<<dim3(LL / 128, 1, BATCH), 256>>>(t, outprojw, xf, n2w, n2b, x2, xn);
    k_pin<<<dim3(LL / 128, 6, BATCH), 256>>>(xn, pinw, h2);
    k_dwconv_glu<<<(BATCH * HID * LL / 4) / 256, 256>>>(h2, dww, g);
    k_pout<<<dim3(LL / 128, 1, BATCH), 256>>>(g, poutw, y2);
    k_fft<<<BATCH * CDIM * 16, 128>>>(y2, x2, Kc, out);

    (void)in_sizes; (void)n_in; (void)out_size;
}

// round 8
// speedup vs baseline: 1.5583x; 1.0591x over previous
#include <cuda_runtime.h>
#include <math.h>
#include <stdint.h>

// ---------------- problem constants ----------------
#define BATCH 2
#define CDIM 64
#define DI   128          // D_INNER
#define HH   128
#define WW   128
#define LL   (HH*WW)      // 16384
#define NCHC 20           // DT_RANK + 2*D_STATE
#define DTR  4
#define DST  8
#define HID  192
#define H2C  384
#define CHUNK   128
#define NCHUNK  (LL/CHUNK)   // 128

// ---------------- scratch (device globals; no allocation allowed) ----------------
__device__ float g_xf   [BATCH*CDIM*LL];
__device__ float g_xn   [BATCH*CDIM*LL];
__device__ float g_xin  [BATCH*DI*LL];
__device__ float g_z    [BATCH*DI*LL];
__device__ float g_xs   [BATCH*DI*LL];
__device__ float g_dbl0 [BATCH*NCHC*LL];
__device__ float g_dtr  [BATCH*DTR*LL];
__device__ float g_bc   [BATCH*LL*16];          // [b][p][0..7]=B, [8..15]=C
__device__ float g_delta[BATCH*DI*LL];
__device__ float g_y    [BATCH*DI*LL];
__device__ float g_t    [BATCH*DI*LL];
__device__ float g_x2   [BATCH*CDIM*LL];
__device__ float g_h2   [BATCH*H2C*LL];
__device__ float g_g    [BATCH*HID*LL];
__device__ float g_y2   [BATCH*CDIM*LL];
__device__ float g_P    [BATCH*DI*NCHUNK*DST];
__device__ float g_S    [BATCH*DI*NCHUNK*DST];
__device__ float g_hin  [BATCH*DI*NCHUNK*DST];
__device__ float g_K    [CDIM*64];              // per-channel 8x8 circular-conv kernel

// twiddles for 8-point DFT
__device__ __constant__ float C8[8] = {1.f, 0.70710678118654752f, 0.f, -0.70710678118654752f,
                                      -1.f, -0.70710678118654752f, 0.f, 0.70710678118654752f};
__device__ __constant__ float S8[8] = {0.f, 0.70710678118654752f, 1.f, 0.70710678118654752f,
                                       0.f, -0.70710678118654752f, -1.f, -0.70710678118654752f};

__device__ __forceinline__ float gelu_f(float x) {
    return 0.5f * x * (1.0f + erff(x * 0.70710678118654752f));
}
__device__ __forceinline__ float softplus_f(float x) {
    return (x > 20.f) ? x : log1pf(__expf(x));
}
__device__ __forceinline__ uint32_t f2tf(float f) {
    uint32_t u;
    asm("cvt.rna.tf32.f32 %0, %1;" : "=r"(u) : "f"(f));
    return u;
}

// =====================================================================
// tf32 MMA tile core: block tile 64 outs x 128 px, 256 threads = 8 warps.
// warp (wo = warp>>1 in [0,4), wp = warp&1): 16 outs x 64 px via 8 n-tiles
// of m16n8k8. K chunked by 32. smem padded to avoid bank conflicts:
// s_x: [32][132] (pixels), s_w: [64][36] (weights), tf32 bits.
// Pool layout (floats): s_x = pool[0..4224), s_w = pool[4224..6528),
// s_out (epilogue stage) = pool[0..8192).
// =====================================================================
#define SX_STR 132
#define SW_STR 36
#define POOLN  8192

template<int K>
__device__ __forceinline__ void mma_tile_core(const float* __restrict__ Xb,
                                              const float* __restrict__ Wo,
                                              uint32_t* s_pool,
                                              float (&d)[8][4]) {
    uint32_t* s_x = s_pool;
    uint32_t* s_w = s_pool + 32 * SX_STR;
    const int t = threadIdx.x;
    const int lane = t & 31, warp = t >> 5;
    const int wo = warp >> 1, wp = warp & 1;
    #pragma unroll
    for (int j = 0; j < 8; j++) { d[j][0] = d[j][1] = d[j][2] = d[j][3] = 0.f; }

    for (int kc = 0; kc < K; kc += 32) {
        __syncthreads();
        // fill x tile: 32 k-rows x 128 px
        {
            const int px4 = t & 31, k0 = t >> 5;
            #pragma unroll
            for (int r = 0; r < 4; r++) {
                int k = k0 + r * 8;
                float4 v = *(const float4*)(Xb + (long)(kc + k) * LL + px4 * 4);
                uint32_t* dst = s_x + k * SX_STR + px4 * 4;
                dst[0] = f2tf(v.x); dst[1] = f2tf(v.y);
                dst[2] = f2tf(v.z); dst[3] = f2tf(v.w);
            }
        }
        // fill w tile: 64 o-rows x 32 k
        {
            const int o = t >> 2, q = t & 3;
            #pragma unroll
            for (int r = 0; r < 2; r++) {
                int c = q * 8 + r * 4;
                float4 v = *(const float4*)(Wo + (long)o * K + kc + c);
                uint32_t* dst = s_w + o * SW_STR + c;
                dst[0] = f2tf(v.x); dst[1] = f2tf(v.y);
                dst[2] = f2tf(v.z); dst[3] = f2tf(v.w);
            }
        }
        __syncthreads();
        #pragma unroll
        for (int ks = 0; ks < 4; ks++) {
            const int kb = ks * 8;
            const int ar0 = wo * 16 + (lane >> 2);
            uint32_t a0 = s_w[ar0 * SW_STR + kb + (lane & 3)];
            uint32_t a1 = s_w[(ar0 + 8) * SW_STR + kb + (lane & 3)];
            uint32_t a2 = s_w[ar0 * SW_STR + kb + (lane & 3) + 4];
            uint32_t a3 = s_w[(ar0 + 8) * SW_STR + kb + (lane & 3) + 4];
            #pragma unroll
            for (int j = 0; j < 8; j++) {
                const int pb = wp * 64 + j * 8 + (lane >> 2);
                uint32_t b0 = s_x[(kb + (lane & 3)) * SX_STR + pb];
                uint32_t b1 = s_x[(kb + 4 + (lane & 3)) * SX_STR + pb];
                asm volatile(
                    "mma.sync.aligned.m16n8k8.row.col.f32.tf32.tf32.f32 "
                    "{%0,%1,%2,%3}, {%4,%5,%6,%7}, {%8,%9}, {%0,%1,%2,%3};"
                    : "+f"(d[j][0]), "+f"(d[j][1]), "+f"(d[j][2]), "+f"(d[j][3])
                    : "r"(a0), "r"(a1), "r"(a2), "r"(a3), "r"(b0), "r"(b1));
            }
        }
    }
    __syncthreads();   // s_x/s_w dead; pool reusable as s_out
}

// stage D frags into s_out[64][128]
__device__ __forceinline__ void stage_out(float (&d)[8][4], float* s_out) {
    const int t = threadIdx.x;
    const int lane = t & 31, warp = t >> 5;
    const int wo = warp >> 1, wp = warp & 1;
    const int r0 = wo * 16 + (lane >> 2);
    #pragma unroll
    for (int j = 0; j < 8; j++) {
        const int pc = wp * 64 + j * 8 + (lane & 3) * 2;
        s_out[r0 * 128 + pc]           = d[j][0];
        s_out[r0 * 128 + pc + 1]       = d[j][1];
        s_out[(r0 + 8) * 128 + pc]     = d[j][2];
        s_out[(r0 + 8) * 128 + pc + 1] = d[j][3];
    }
}

// ---------------- K1: in_proj 64->256, split into xin / z ----------------
__global__ void __launch_bounds__(256) k_inproj(const float* __restrict__ xn,
                                                const float* __restrict__ W,
                                                float* __restrict__ xin,
                                                float* __restrict__ z) {
    __shared__ uint32_t s_pool[POOLN];
    const int b = blockIdx.z, oz = blockIdx.y, p0 = blockIdx.x * 128;
    float d[8][4];
    mma_tile_core<64>(xn + (long)b * CDIM * LL + p0, W + oz * 64 * 64, s_pool, d);
    float* s_out = (float*)s_pool;
    stage_out(d, s_out);
    __syncthreads();
    const int t = threadIdx.x, col4 = t & 31, row0 = t >> 5;
    #pragma unroll
    for (int r = 0; r < 8; r++) {
        int row = row0 + r * 8;
        float4 v = *(const float4*)(s_out + row * 128 + col4 * 4);
        int og = oz * 64 + row;
        float* dst = (og < DI) ? xin + ((long)b * DI + og) * LL
                               : z + ((long)b * DI + og - DI) * LL;
        *(float4*)(dst + p0 + col4 * 4) = v;
    }
}

// ---------------- K8: pin 64->384 ----------------
__global__ void __launch_bounds__(256) k_pin(const float* __restrict__ xn,
                                             const float* __restrict__ W,
                                             float* __restrict__ h2) {
    __shared__ uint32_t s_pool[POOLN];
    const int b = blockIdx.z, oz = blockIdx.y, p0 = blockIdx.x * 128;
    float d[8][4];
    mma_tile_core<64>(xn + (long)b * CDIM * LL + p0, W + oz * 64 * 64, s_pool, d);
    float* s_out = (float*)s_pool;
    stage_out(d, s_out);
    __syncthreads();
    const int t = threadIdx.x, col4 = t & 31, row0 = t >> 5;
    #pragma unroll
    for (int r = 0; r < 8; r++) {
        int row = row0 + r * 8;
        float4 v = *(const float4*)(s_out + row * 128 + col4 * 4);
        int og = oz * 64 + row;
        *(float4*)(h2 + ((long)b * H2C + og) * LL + p0 + col4 * 4) = v;
    }
}

// ---------------- K6b: out_proj 128->64 + residual + FUSED rms(norm2) ----------------
__global__ void __launch_bounds__(256) k_outproj(const float* __restrict__ tin,
                                                 const float* __restrict__ W,
                                                 const float* __restrict__ xf,
                                                 const float* __restrict__ n2w,
                                                 const float* __restrict__ n2b,
                                                 float* __restrict__ x2,
                                                 float* __restrict__ xn) {
    __shared__ uint32_t s_pool[POOLN];
    __shared__ float s_red[8 * 128];
    __shared__ float s_rs[128];
    const int b = blockIdx.z, p0 = blockIdx.x * 128;
    float d[8][4];
    mma_tile_core<128>(tin + (long)b * DI * LL + p0, W, s_pool, d);
    float* s_out = (float*)s_pool;
    stage_out(d, s_out);
    __syncthreads();
    const int t = threadIdx.x, col4 = t & 31, row0 = t >> 5;
    float4 ssq = make_float4(0.f, 0.f, 0.f, 0.f);
    #pragma unroll
    for (int r = 0; r < 8; r++) {
        int row = row0 + r * 8;
        float4 v = *(const float4*)(s_out + row * 128 + col4 * 4);
        float4 res = *(const float4*)(xf + ((long)b * CDIM + row) * LL + p0 + col4 * 4);
        v.x += res.x; v.y += res.y; v.z += res.z; v.w += res.w;
        *(float4*)(s_out + row * 128 + col4 * 4) = v;   // only this thread re-reads these cells
        *(float4*)(x2 + ((long)b * CDIM + row) * LL + p0 + col4 * 4) = v;
        ssq.x += v.x * v.x; ssq.y += v.y * v.y; ssq.z += v.z * v.z; ssq.w += v.w * v.w;
    }
    *(float4*)(s_red + row0 * 128 + col4 * 4) = ssq;
    __syncthreads();
    if (t < 128) {
        float s = 0.f;
        #pragma unroll
        for (int g = 0; g < 8; g++) s += s_red[g * 128 + t];
        s_rs[t] = rsqrtf(s * (1.0f / CDIM) + 1e-6f);
    }
    __syncthreads();
    float4 rs4 = *(const float4*)(s_rs + col4 * 4);
    #pragma unroll
    for (int r = 0; r < 8; r++) {
        int row = row0 + r * 8;
        float4 v = *(const float4*)(s_out + row * 128 + col4 * 4);
        float wj = n2w[row], bj = n2b[row];
        float4 o;
        o.x = v.x * rs4.x * wj + bj;
        o.y = v.y * rs4.y * wj + bj;
        o.z = v.z * rs4.z * wj + bj;
        o.w = v.w * rs4.w * wj + bj;
        *(float4*)(xn + ((long)b * CDIM + row) * LL + p0 + col4 * 4) = o;
    }
}

// ---------------- K10: pout 192->64 ----------------
__global__ void __launch_bounds__(256) k_pout(const float* __restrict__ gg,
                                              const float* __restrict__ W,
                                              float* __restrict__ y2) {
    __shared__ uint32_t s_pool[POOLN];
    const int b = blockIdx.z, p0 = blockIdx.x * 128;
    float d[8][4];
    mma_tile_core<192>(gg + (long)b * HID * LL + p0, W, s_pool, d);
    float* s_out = (float*)s_pool;
    stage_out(d, s_out);
    __syncthreads();
    const int t = threadIdx.x, col4 = t & 31, row0 = t >> 5;
    #pragma unroll
    for (int r = 0; r < 8; r++) {
        int row = row0 + r * 8;
        float4 v = *(const float4*)(s_out + row * 128 + col4 * 4);
        *(float4*)(y2 + ((long)b * CDIM + row) * LL + p0 + col4 * 4) = v;
    }
}

// ---------------- K3a: x_proj 128->20 (SIMT; already fast) ----------------
__global__ void __launch_bounds__(256) k_xproj(const float* __restrict__ xs,
                                               const float* __restrict__ Wg,
                                               float* __restrict__ out) {
    __shared__ float s_x[DI * 64];
    __shared__ float s_w[DI * NCHC];
    const int t = threadIdx.x;
    const int b = blockIdx.y, p0 = blockIdx.x * 64;
    for (int i = t; i < DI * NCHC; i += 256) {
        int c = i % NCHC, d = i / NCHC;
        s_w[i] = Wg[c * DI + d];
    }
    const float* Xb = xs + (long)b * DI * LL + p0;
    for (int i = t; i < DI * 16; i += 256) {
        int ch = i >> 4, c4 = i & 15;
        *(float4*)(s_x + ch * 64 + c4 * 4) = *(const float4*)(Xb + ch * LL + c4 * 4);
    }
    __syncthreads();
    const int px = t & 63, kg = t >> 6;
    float acc[NCHC];
    #pragma unroll
    for (int c = 0; c < NCHC; c++) acc[c] = 0.f;
    #pragma unroll 8
    for (int c = 0; c < 32; c++) {
        int ch = kg * 32 + c;
        float xv = s_x[ch * 64 + px];
        const float* wr = s_w + ch * NCHC;
        #pragma unroll
        for (int i = 0; i < 5; i++) {
            float4 w4 = *(const float4*)(wr + i * 4);
            acc[4*i+0] += w4.x * xv; acc[4*i+1] += w4.y * xv;
            acc[4*i+2] += w4.z * xv; acc[4*i+3] += w4.w * xv;
        }
    }
    __syncthreads();
    float* s_r = s_x;
    #pragma unroll
    for (int o = 0; o < NCHC; o++) s_r[(kg * NCHC + o) * 64 + px] = acc[o];
    __syncthreads();
    #pragma unroll
    for (int q = 0; q < 5; q++) {
        int idx = t + q * 256;
        int o = idx >> 6, px2 = idx & 63;
        float sum = s_r[(0 * NCHC + o) * 64 + px2] + s_r[(1 * NCHC + o) * 64 + px2]
                  + s_r[(2 * NCHC + o) * 64 + px2] + s_r[(3 * NCHC + o) * 64 + px2];
        out[(long)b * NCHC * LL + o * LL + p0 + px2] = sum;
    }
}

// ---------------- K0: flip + rmsnorm(norm1), keep flipped copy ----------------
__global__ void k_flip_rms(const float* __restrict__ x, const float* __restrict__ w,
                           const float* __restrict__ bb, float* __restrict__ xf,
                           float* __restrict__ xn) {
    int p = blockIdx.x * blockDim.x + threadIdx.x;
    int b = blockIdx.y;
    if (p >= LL) return;
    float v[CDIM];
    float ss = 0.f;
    int src = b * CDIM * LL + (LL - 1 - p);
    #pragma unroll
    for (int c = 0; c < CDIM; c++) { float t = x[src + c * LL]; v[c] = t; ss += t * t; }
    float rs = rsqrtf(ss * (1.0f / CDIM) + 1e-6f);
    int dst = b * CDIM * LL + p;
    #pragma unroll
    for (int c = 0; c < CDIM; c++) {
        xf[dst + c * LL] = v[c];
        xn[dst + c * LL] = v[c] * rs * w[c] + bb[c];
    }
}

// ---------------- K2: depthwise 3x3 + bias + gelu, 4px/thread ----------------
__global__ void __launch_bounds__(256) k_dwconv2_gelu(const float* __restrict__ xin,
                                                      const float* __restrict__ cw,
                                                      const float* __restrict__ cb,
                                                      float* __restrict__ xs) {
    int q = blockIdx.x * blockDim.x + threadIdx.x;
    int pq = q & (LL / 4 - 1);
    int d = (q >> 12) & (DI - 1);
    int b = q >> 19;
    int p = pq * 4;
    int h = p >> 7, w0 = p & 127;
    const float* in = xin + ((long)b * DI + d) * LL;
    const float* k = cw + d * 9;
    float bias = cb[d];
    float a0 = bias, a1 = bias, a2 = bias, a3 = bias;
    #pragma unroll
    for (int dh = -1; dh <= 1; dh++) {
        int h2 = h + dh; if ((unsigned)h2 >= HH) continue;
        const float* row = in + h2 * WW;
        float k0 = k[(dh + 1) * 3], k1 = k[(dh + 1) * 3 + 1], k2 = k[(dh + 1) * 3 + 2];
        float l = (w0 > 0) ? row[w0 - 1] : 0.f;
        float4 m = *(const float4*)(row + w0);
        float r = (w0 + 4 < WW) ? row[w0 + 4] : 0.f;
        a0 += l   * k0 + m.x * k1 + m.y * k2;
        a1 += m.x * k0 + m.y * k1 + m.z * k2;
        a2 += m.y * k0 + m.z * k1 + m.w * k2;
        a3 += m.z * k0 + m.w * k1 + r   * k2;
    }
    float4 o = make_float4(gelu_f(a0), gelu_f(a1), gelu_f(a2), gelu_f(a3));
    *(float4*)(xs + ((long)b * DI + d) * LL + p) = o;
}

// ---------------- K3b: depthwise 1d conv (k=7, pad 3) + bias ----------------
__global__ void k_dwconv1(const float* __restrict__ in, const float* __restrict__ cw,
                          const float* __restrict__ cb, float* __restrict__ dtr,
                          float* __restrict__ bc) {
    int idx = blockIdx.x * blockDim.x + threadIdx.x;
    if (idx >= BATCH * NCHC * LL) return;
    int p = idx % LL;
    int c = (idx / LL) % NCHC;
    int b = idx / (LL * NCHC);
    const float* ip = in + (b * NCHC + c) * LL;
    const float* k = cw + c * 7;
    float acc = cb[c];
    #pragma unroll
    for (int t = -3; t <= 3; t++) {
        int pp = p + t;
        if ((unsigned)pp < LL) acc += ip[pp] * k[t + 3];
    }
    if (c < DTR) dtr[(b * DTR + c) * LL + p] = acc;
    else         bc[((long)b * LL + p) * 16 + (c - DTR)] = acc;
}

// ---------------- K4: dt projection + softplus -> delta ----------------
__global__ void k_delta(const float* __restrict__ dtr, const float* __restrict__ dtw,
                        const float* __restrict__ dtb, float* __restrict__ delta) {
    __shared__ float sw[DI * 4];
    __shared__ float sb[DI];
    for (int i = threadIdx.x; i < DI * 4; i += blockDim.x) sw[i] = dtw[i];
    for (int i = threadIdx.x; i < DI; i += blockDim.x) sb[i] = dtb[i];
    __syncthreads();
    int px = blockIdx.x * blockDim.x + threadIdx.x;
    int b = blockIdx.y;
    if (px >= LL) return;
    const float* rp = dtr + b * DTR * LL + px;
    float r0 = rp[0], r1 = rp[LL], r2 = rp[2 * LL], r3 = rp[3 * LL];
    float* op = delta + b * DI * LL + px;
    #pragma unroll 4
    for (int d = 0; d < DI; d++) {
        float4 w4 = ((const float4*)sw)[d];
        float s = r0 * w4.x + r1 * w4.y + r2 * w4.z + r3 * w4.w + sb[d];
        op[d * LL] = softplus_f(s);
    }
}

// ---------------- K5a: chunked scan pass A (local P, S) ----------------
__global__ void k_scanA(const float* __restrict__ delta, const float* __restrict__ xs,
                        const float* __restrict__ bc, const float* __restrict__ Alog,
                        float* __restrict__ P, float* __restrict__ S) {
    int tid = blockIdx.x * blockDim.x + threadIdx.x;
    int n = tid & 7;
    int r = tid >> 3;
    int chunk = r & (NCHUNK - 1);
    int bd = r >> 7;
    int d = bd & (DI - 1);
    float An = -__expf(Alog[d * DST + n]);
    int b = bd >> 7;
    const float* dp = delta + bd * LL + chunk * CHUNK;
    const float* xp = xs + bd * LL + chunk * CHUNK;
    const float* bp = bc + ((long)b * LL + chunk * CHUNK) * 16 + n;
    float Pv = 1.f, Sv = 0.f;
    #pragma unroll 4
    for (int t = 0; t < CHUNK; t++) {
        float dl = dp[t], xv = xp[t];
        float a = __expf(dl * An);
        float bx = dl * xv * bp[t * 16];
        Pv *= a;
        Sv = a * Sv + bx;
    }
    int o = (bd * NCHUNK + chunk) * 8 + n;
    P[o] = Pv; S[o] = Sv;
}

// ---------------- K5b: scan across chunks ----------------
__global__ void k_scanB(const float* __restrict__ P, const float* __restrict__ S,
                        float* __restrict__ hin) {
    int tid = blockIdx.x * blockDim.x + threadIdx.x;
    int n = tid & 7;
    int bd = tid >> 3;
    float h = 0.f;
    int base = bd * NCHUNK * 8 + n;
    for (int c = 0; c < NCHUNK; c++) {
        int o = base + c * 8;
        hin[o] = h;
        h = P[o] * h + S[o];
    }
}

// ---------------- K5c: pass C — recompute with true h_in, emit y ----------------
__global__ void k_scanC(const float* __restrict__ delta, const float* __restrict__ xs,
                        const float* __restrict__ bc, const float* __restrict__ Alog,
                        const float* __restrict__ Ds, const float* __restrict__ hin,
                        float* __restrict__ y) {
    int tid = blockIdx.x * blockDim.x + threadIdx.x;
    int n = tid & 7;
    int r = tid >> 3;
    int chunk = r & (NCHUNK - 1);
    int bd = r >> 7;
    int d = bd & (DI - 1);
    int b = bd >> 7;
    float An = -__expf(Alog[d * DST + n]);
    float Dd = Ds[d];
    const float* dp = delta + bd * LL + chunk * CHUNK;
    const float* xp = xs + bd * LL + chunk * CHUNK;
    const float* bp = bc + ((long)b * LL + chunk * CHUNK) * 16 + n;
    const float* cp = bp + 8;
    float h = hin[(bd * NCHUNK + chunk) * 8 + n];
    float* yp = y + bd * LL + chunk * CHUNK;
    #pragma unroll 2
    for (int t = 0; t < CHUNK; t++) {
        float dl = dp[t], xv = xp[t];
        float a = __expf(dl * An);
        float bx = dl * xv * bp[t * 16];
        h = a * h + bx;
        float yv = h * cp[t * 16];
        yv += __shfl_xor_sync(0xffffffffu, yv, 1);
        yv += __shfl_xor_sync(0xffffffffu, yv, 2);
        yv += __shfl_xor_sync(0xffffffffu, yv, 4);
        if (n == 0) yp[t] = yv + Dd * xv;
    }
}

// ---------------- K6a: LayerNorm(d=128) * gelu(z), 2 threads/px ----------------
__global__ void __launch_bounds__(256) k_lngelu(const float* __restrict__ y,
                                                const float* __restrict__ z,
                                                const float* __restrict__ w,
                                                const float* __restrict__ bb,
                                                float* __restrict__ tout) {
    __shared__ float sww[DI], sbb[DI];
    __shared__ float s_s[256], s_s2[256];
    int t = threadIdx.x;
    if (t < DI) { sww[t] = w[t]; sbb[t] = bb[t]; }
    int px = blockIdx.x * 128 + (t & 127);
    int half = t >> 7;
    int b = blockIdx.y;
    const float* yp = y + (long)b * DI * LL + half * 64 * LL + px;
    float v[64];
    float s = 0.f, s2 = 0.f;
    #pragma unroll 8
    for (int d = 0; d < 64; d++) { float u = yp[d * LL]; v[d] = u; s += u; s2 += u * u; }
    s_s[t] = s; s_s2[t] = s2;
    __syncthreads();
    int other = t ^ 128;
    float S = s_s[t] + s_s[other];
    float S2 = s_s2[t] + s_s2[other];
    float mu = S * (1.f / DI);
    float var = fmaxf(S2 * (1.f / DI) - mu * mu, 0.f);
    float rs = rsqrtf(var + 1e-5f);
    const float* zp = z + (long)b * DI * LL + half * 64 * LL + px;
    float* op = tout + (long)b * DI * LL + half * 64 * LL + px;
    #pragma unroll 8
    for (int d = 0; d < 64; d++) {
        float val = (v[d] - mu) * rs * sww[half * 64 + d] + sbb[half * 64 + d];
        op[d * LL] = val * gelu_f(zp[d * LL]);
    }
}

// ---------------- K9: depthwise 3x3 + GLU gate, 4px/thread ----------------
__global__ void __launch_bounds__(256) k_dwconv_glu(const float* __restrict__ h2,
                                                    const float* __restrict__ dw,
                                                    float* __restrict__ g) {
    int q = blockIdx.x * blockDim.x + threadIdx.x;
    int pq = q & (LL / 4 - 1);
    int o = (q >> 12) % HID;
    int b = q / (HID * (LL / 4));
    int p = pq * 4;
    int h = p >> 7, w0 = p & 127;
    const float* inA = h2 + ((long)b * H2C + o) * LL;
    const float* inB = h2 + ((long)b * H2C + HID + o) * LL;
    const float* kA = dw + o * 9;
    const float* kB = dw + (HID + o) * 9;
    float a0 = 0.f, a1 = 0.f, a2 = 0.f, a3 = 0.f;
    float c0 = 0.f, c1 = 0.f, c2 = 0.f, c3 = 0.f;
    #pragma unroll
    for (int dh = -1; dh <= 1; dh++) {
        int h2i = h + dh; if ((unsigned)h2i >= HH) continue;
        const float* rowA = inA + h2i * WW;
        const float* rowB = inB + h2i * WW;
        float ka0 = kA[(dh+1)*3], ka1 = kA[(dh+1)*3+1], ka2 = kA[(dh+1)*3+2];
        float kb0 = kB[(dh+1)*3], kb1 = kB[(dh+1)*3+1], kb2 = kB[(dh+1)*3+2];
        float la = (w0 > 0) ? rowA[w0 - 1] : 0.f;
        float lb = (w0 > 0) ? rowB[w0 - 1] : 0.f;
        float4 ma = *(const float4*)(rowA + w0);
        float4 mb = *(const float4*)(rowB + w0);
        float ra = (w0 + 4 < WW) ? rowA[w0 + 4] : 0.f;
        float rb = (w0 + 4 < WW) ? rowB[w0 + 4] : 0.f;
        a0 += la   * ka0 + ma.x * ka1 + ma.y * ka2;
        a1 += ma.x * ka0 + ma.y * ka1 + ma.z * ka2;
        a2 += ma.y * ka0 + ma.z * ka1 + ma.w * ka2;
        a3 += ma.z * ka0 + ma.w * ka1 + ra   * ka2;
        c0 += lb   * kb0 + mb.x * kb1 + mb.y * kb2;
        c1 += mb.x * kb0 + mb.y * kb1 + mb.z * kb2;
        c2 += mb.y * kb0 + mb.z * kb1 + mb.w * kb2;
        c3 += mb.z * kb0 + mb.w * kb1 + rb   * kb2;
    }
    float4 out4 = make_float4(gelu_f(a0) * c0, gelu_f(a1) * c1,
                              gelu_f(a2) * c2, gelu_f(a3) * c3);
    *(float4*)(g + ((long)b * HID + o) * LL + p) = out4;
}

// ---------------- K11a: precompute per-channel circular-conv kernel from fft_p ----------------
__global__ void k_fftker(const float* __restrict__ fp, float* __restrict__ Kout) {
    int c = threadIdx.x;
    if (c >= CDIM) return;
    const float* sp = fp + c * 40;
    float Xr[8][5];
    #pragma unroll
    for (int h = 0; h < 8; h++)
        #pragma unroll
        for (int w = 0; w < 5; w++) Xr[h][w] = sp[h * 5 + w];
    float Kr[8][5], Ki[8][5];
    #pragma unroll
    for (int w = 0; w < 5; w++) {
        #pragma unroll
        for (int h = 0; h < 8; h++) {
            float sr = 0.f, si = 0.f;
            #pragma unroll
            for (int m = 0; m < 8; m++) {
                int k = (h * m) & 7;
                sr += Xr[m][w] * C8[k];
                si += Xr[m][w] * S8[k];
            }
            Kr[h][w] = sr; Ki[h][w] = si;
        }
    }
    #pragma unroll
    for (int i = 0; i < 8; i++) {
        #pragma unroll
        for (int j = 0; j < 8; j++) {
            float v = Kr[i][0] + ((j & 1) ? -Kr[i][4] : Kr[i][4]);
            #pragma unroll
            for (int w = 1; w < 4; w++) {
                int k = (w * j) & 7;
                v += 2.f * (Kr[i][w] * C8[k] - Ki[i][w] * S8[k]);
            }
            Kout[c * 64 + i * 8 + j] = v * (1.f / 64.f);
        }
    }
}

// ---------------- K11b: per-patch circular conv with K_c + residual ----------------
__global__ void __launch_bounds__(128) k_fft(const float* __restrict__ y2,
                                             const float* __restrict__ x2,
                                             const float* __restrict__ Kg,
                                             float* __restrict__ out) {
    __shared__ float s_P[8 * 128];
    __shared__ float s_K[64];
    int blk = blockIdx.x;
    int ph = blk & 15;
    int bc = blk >> 4;
    int c = bc & (CDIM - 1);
    const float* base = y2 + (long)bc * LL + (ph * 8) * WW;
    int t = threadIdx.x;
    for (int i = t; i < 256; i += 128) {
        int r = i >> 5, c4 = i & 31;
        *(float4*)(s_P + r * 128 + c4 * 4) = *(const float4*)(base + r * WW + c4 * 4);
    }
    if (t < 64) s_K[t] = Kg[c * 64 + t];
    __syncthreads();
    int pw = t & 15;
    int i = t >> 4;
    float acc[8] = {0.f, 0.f, 0.f, 0.f, 0.f, 0.f, 0.f, 0.f};
    #pragma unroll
    for (int a = 0; a < 8; a++) {
        float4 p0 = *(const float4*)(s_P + a * 128 + pw * 8);
        float4 p1 = *(const float4*)(s_P + a * 128 + pw * 8 + 4);
        float pa[8] = {p0.x, p0.y, p0.z, p0.w, p1.x, p1.y, p1.z, p1.w};
        int krow = (i - a) & 7;
        float4 k0 = *(const float4*)(s_K + krow * 8);
        float4 k1 = *(const float4*)(s_K + krow * 8 + 4);
        float kr[8] = {k0.x, k0.y, k0.z, k0.w, k1.x, k1.y, k1.z, k1.w};
        #pragma unroll
        for (int bb = 0; bb < 8; bb++) {
            #pragma unroll
            for (int j = 0; j < 8; j++)
                acc[j] += pa[bb] * kr[(j - bb) & 7];
        }
    }
    const float* xp = x2 + (long)bc * LL + (ph * 8 + i) * WW + pw * 8;
    float* op = out + (long)bc * LL + (ph * 8 + i) * WW + pw * 8;
    float4 r0 = *(const float4*)(xp);
    float4 r1 = *(const float4*)(xp + 4);
    float4 o0 = make_float4(acc[0] + r0.x, acc[1] + r0.y, acc[2] + r0.z, acc[3] + r0.w);
    float4 o1 = make_float4(acc[4] + r1.x, acc[5] + r1.y, acc[6] + r1.z, acc[7] + r1.w);
    *(float4*)(op) = o0;
    *(float4*)(op + 4) = o1;
}

// ---------------- host launch ----------------
extern "C" void kernel_launch(void* const* d_in, const int* in_sizes, int n_in,
                              void* d_out, int out_size) {
    const float* x        = (const float*)d_in[0];
    const float* n1w      = (const float*)d_in[1];
    const float* n1b      = (const float*)d_in[2];
    const float* inprojw  = (const float*)d_in[3];
    const float* conv2dw  = (const float*)d_in[4];
    const float* conv2db  = (const float*)d_in[5];
    const float* xprojw   = (const float*)d_in[6];
    const float* xconvw   = (const float*)d_in[7];
    const float* xconvb   = (const float*)d_in[8];
    const float* dtpw     = (const float*)d_in[9];
    const float* dtpb     = (const float*)d_in[10];
    const float* Alogs    = (const float*)d_in[11];
    const float* Ds       = (const float*)d_in[12];
    const float* onw      = (const float*)d_in[13];
    const float* onb      = (const float*)d_in[14];
    const float* outprojw = (const float*)d_in[15];
    const float* n2w      = (const float*)d_in[16];
    const float* n2b      = (const float*)d_in[17];
    const float* pinw     = (const float*)d_in[18];
    const float* dww      = (const float*)d_in[19];
    const float* fftp     = (const float*)d_in[20];
    const float* poutw    = (const float*)d_in[21];
    float* out = (float*)d_out;

    float *xf, *xn, *xin, *z, *xs, *dbl0, *dtr, *bc, *delta, *y, *t, *x2, *h2, *g, *y2, *P, *S, *hin, *Kc;
    cudaGetSymbolAddress((void**)&xf, g_xf);
    cudaGetSymbolAddress((void**)&xn, g_xn);
    cudaGetSymbolAddress((void**)&xin, g_xin);
    cudaGetSymbolAddress((void**)&z, g_z);
    cudaGetSymbolAddress((void**)&xs, g_xs);
    cudaGetSymbolAddress((void**)&dbl0, g_dbl0);
    cudaGetSymbolAddress((void**)&dtr, g_dtr);
    cudaGetSymbolAddress((void**)&bc, g_bc);
    cudaGetSymbolAddress((void**)&delta, g_delta);
    cudaGetSymbolAddress((void**)&y, g_y);
    cudaGetSymbolAddress((void**)&t, g_t);
    cudaGetSymbolAddress((void**)&x2, g_x2);
    cudaGetSymbolAddress((void**)&h2, g_h2);
    cudaGetSymbolAddress((void**)&g, g_g);
    cudaGetSymbolAddress((void**)&y2, g_y2);
    cudaGetSymbolAddress((void**)&P, g_P);
    cudaGetSymbolAddress((void**)&S, g_S);
    cudaGetSymbolAddress((void**)&hin, g_hin);
    cudaGetSymbolAddress((void**)&Kc, g_K);

    dim3 px128(LL / 128, BATCH);

    k_fftker<<<1, 64>>>(fftp, Kc);   // independent; fires early
    k_flip_rms<<<px128, 128>>>(x, n1w, n1b, xf, xn);
    k_inproj<<<dim3(LL / 128, 4, BATCH), 256>>>(xn, inprojw, xin, z);
    k_dwconv2_gelu<<<(BATCH * DI * LL / 4) / 256, 256>>>(xin, conv2dw, conv2db, xs);
    k_xproj<<<dim3(LL / 64, BATCH), 256>>>(xs, xprojw, dbl0);
    k_dwconv1<<<(BATCH * NCHC * LL) / 256, 256>>>(dbl0, xconvw, xconvb, dtr, bc);
    k_delta<<<px128, 128>>>(dtr, dtpw, dtpb, delta);
    k_scanA<<<(BATCH * DI * NCHUNK * DST) / 256, 256>>>(delta, xs, bc, Alogs, P, S);
    k_scanB<<<(BATCH * DI * DST) / 256, 256>>>(P, S, hin);
    k_scanC<<<(BATCH * DI * NCHUNK * DST) / 256, 256>>>(delta, xs, bc, Alogs, Ds, hin, y);
    k_lngelu<<<dim3(LL / 128, BATCH), 256>>>(y, z, onw, onb, t);
    k_outproj<<<dim3(LL / 128, 1, BATCH), 256>>>(t, outprojw, xf, n2w, n2b, x2, xn);
    k_pin<<<dim3(LL / 128, 6, BATCH), 256>>>(xn, pinw, h2);
    k_dwconv_glu<<<(BATCH * HID * LL / 4) / 256, 256>>>(h2, dww, g);
    k_pout<<<dim3(LL / 128, 1, BATCH), 256>>>(g, poutw, y2);
    k_fft<<<BATCH * CDIM * 16, 128>>>(y2, x2, Kc, out);

    (void)in_sizes; (void)n_in; (void)out_size;
}